// round 7
// baseline (speedup 1.0000x reference)
#include <cuda_runtime.h>
#include <cuda_bf16.h>
#include <cuda_fp16.h>
#include <math.h>
#include <stdint.h>

// ---------------------------------------------------------------------------
// Problem constants
// ---------------------------------------------------------------------------
namespace {
constexpr int B   = 128;
constexpr int T   = 31;
constexpr int TP1 = 32;     // T+1
constexpr int E   = 512;
constexpr int H   = 512;
constexpr int V   = 10000;
constexpr int A   = 2048;
constexpr int G4  = 2048;   // 4*H
constexpr int MALL = TP1 * B;   // 4096
constexpr int VPAD = 10240;     // 80 * 128
constexpr int KBF  = 1536;      // 3 * 512 split-bf16 K (pan/pad)
constexpr int KH1  = 512;       // 1-term fp16 K (logits)
constexpr int GRID_R = 296;     // persistent kernel grid (2 CTAs/SM floor)

// scratch layout (floats) inside one __device__ buffer
constexpr size_t XS_OFF   = 0;                              // [TP1][B][E]
constexpr size_t PAN_OFF  = XS_OFF  + (size_t)TP1*B*E;      // [TP1][B][A]
constexpr size_t PAD_OFF  = PAN_OFF + (size_t)TP1*B*A;      // [TP1][B][E]
constexpr size_t H_OFF    = PAD_OFF + (size_t)TP1*B*E;      // [B][H]
constexpr size_t C_OFF    = H_OFF   + (size_t)B*H;          // [B][H]
constexpr size_t ATT_OFF  = C_OFF   + (size_t)B*H;          // [B][A]
constexpr size_t SC_OFF   = ATT_OFF + (size_t)B*A;          // [B][A] h-scores
constexpr size_t GH_OFF   = SC_OFF  + (size_t)B*A;          // [B][G4]
constexpr size_t GX_OFF   = GH_OFF  + (size_t)B*G4;         // [B][G4]
constexpr size_t SLD_OFF  = GX_OFF  + (size_t)B*G4;         // [4][B][E]
constexpr size_t BS_OFF   = SLD_OFF + (size_t)4*B*E;        // [G4]
constexpr size_t BUF_TOTAL = BS_OFF + (size_t)G4;

constexpr int SLAB = B * E;      // 65536, slD slab stride
}

__device__ float g_buf[BUF_TOTAL];
__device__ unsigned g_bar;       // persistent-kernel barrier counter

// bf16 split operand buffers (pan/pad: 3-term)
__device__ __nv_bfloat16 g_xs_bf [(size_t)MALL * KBF];
__device__ __nv_bfloat16 g_wattn_bf[(size_t)A * KBF];
__device__ __nv_bfloat16 g_wattd_bf[(size_t)E * KBF];
// fp16 1-term buffers (logits)
__device__ __half g_hid_h [(size_t)MALL * KH1];
__device__ __half g_wout_h[(size_t)VPAD * KH1];

// ---------------------------------------------------------------------------
// Packed f32x2 FMA helpers
// ---------------------------------------------------------------------------
typedef unsigned long long ull;

__device__ __forceinline__ ull ffma2(ull a, ull b, ull c) {
    ull d;
    asm("fma.rn.f32x2 %0, %1, %2, %3;" : "=l"(d) : "l"(a), "l"(b), "l"(c));
    return d;
}
__device__ __forceinline__ ull dup2(float x) {
    ull d;
    asm("mov.b64 %0, {%1, %1};" : "=l"(d) : "f"(x));
    return d;
}
__device__ __forceinline__ float2 unpk(ull v) {
    float2 r;
    asm("mov.b64 {%0, %1}, %2;" : "=f"(r.x), "=f"(r.y) : "l"(v));
    return r;
}

// ---------------------------------------------------------------------------
// HMMA helpers (sm_80+ PTX)
// ---------------------------------------------------------------------------
__device__ __forceinline__ uint32_t smem_u32(const void* p) {
    uint32_t a;
    asm("{ .reg .u64 t; cvta.to.shared.u64 t, %1; cvt.u32.u64 %0, t; }"
        : "=r"(a) : "l"(p));
    return a;
}
__device__ __forceinline__ void cpa16(uint32_t s, const void* g) {
    asm volatile("cp.async.cg.shared.global [%0], [%1], 16;"
                 :: "r"(s), "l"(g));
}
#define CP_COMMIT() asm volatile("cp.async.commit_group;" ::: "memory")
#define CP_WAIT(N)  asm volatile("cp.async.wait_group %0;" :: "n"(N) : "memory")

#define LDSM4(R0, R1, R2, R3, ADDR) \
    asm volatile("ldmatrix.sync.aligned.m8n8.x4.shared.b16 {%0,%1,%2,%3}, [%4];" \
        : "=r"(R0), "=r"(R1), "=r"(R2), "=r"(R3) : "r"(ADDR))

template<bool FP16>
__device__ __forceinline__ void mma16816(float* d, const uint32_t* a,
                                         uint32_t b0, uint32_t b1) {
    if constexpr (FP16) {
        asm volatile(
            "mma.sync.aligned.m16n8k16.row.col.f32.f16.f16.f32 "
            "{%0,%1,%2,%3}, {%4,%5,%6,%7}, {%8,%9}, {%0,%1,%2,%3};"
            : "+f"(d[0]), "+f"(d[1]), "+f"(d[2]), "+f"(d[3])
            : "r"(a[0]), "r"(a[1]), "r"(a[2]), "r"(a[3]), "r"(b0), "r"(b1));
    } else {
        asm volatile(
            "mma.sync.aligned.m16n8k16.row.col.f32.bf16.bf16.f32 "
            "{%0,%1,%2,%3}, {%4,%5,%6,%7}, {%8,%9}, {%0,%1,%2,%3};"
            : "+f"(d[0]), "+f"(d[1]), "+f"(d[2]), "+f"(d[3])
            : "r"(a[0]), "r"(a[1]), "r"(a[2]), "r"(a[3]), "r"(b0), "r"(b1));
    }
}

namespace {
constexpr int HBK   = 32;
constexpr int HROWB = 80;            // 32 elems * 2B + 16B pad
constexpr int HSTG  = 256 * HROWB;   // 20480 B per stage
constexpr int HSMEM = 3 * HSTG;      // 61440 B
}

template<int KTOT, bool FP16>
__global__ void __launch_bounds__(256, 2)
hmma_gemm(float* __restrict__ C, int ldc, int Nreal,
          const uint16_t* __restrict__ Abf,
          const uint16_t* __restrict__ Bbf,
          const float* __restrict__ bias)
{
    constexpr int NT = KTOT / HBK;
    extern __shared__ __align__(16) char sm[];
    const uint32_t sb = smem_u32(sm);

    const int tid  = threadIdx.x;
    const int wid  = tid >> 5;
    const int lane = tid & 31;
    const int wm   = wid & 1;
    const int wn   = wid >> 1;
    const int row0 = blockIdx.y * 128;
    const int col0 = blockIdx.x * 128;

    const int qr0 = (tid)       >> 2, qc0 = (tid)       & 3;
    const int qr1 = (tid + 256) >> 2, qc1 = (tid + 256) & 3;

    auto LOADG = [&](int t, int stg) {
        const int k0 = t * HBK;
        const uint32_t sa  = sb + stg * HSTG;
        const uint32_t sbm = sa + 128 * HROWB;
        cpa16(sa  + qr0 * HROWB + qc0 * 16,
              Abf + (size_t)(row0 + qr0) * KTOT + k0 + qc0 * 8);
        cpa16(sa  + qr1 * HROWB + qc1 * 16,
              Abf + (size_t)(row0 + qr1) * KTOT + k0 + qc1 * 8);
        cpa16(sbm + qr0 * HROWB + qc0 * 16,
              Bbf + (size_t)(col0 + qr0) * KTOT + k0 + qc0 * 8);
        cpa16(sbm + qr1 * HROWB + qc1 * 16,
              Bbf + (size_t)(col0 + qr1) * KTOT + k0 + qc1 * 8);
    };

    float acc[4][4][4];
#pragma unroll
    for (int i = 0; i < 4; ++i)
#pragma unroll
        for (int j = 0; j < 4; ++j)
#pragma unroll
            for (int q = 0; q < 4; ++q) acc[i][j][q] = 0.f;

    const int lr  = lane & 15;
    const int lkb = (lane >> 4) * 16;

    LOADG(0, 0); CP_COMMIT();
    LOADG(1, 1); CP_COMMIT();

    for (int t = 0; t < NT; ++t) {
        if (t + 1 < NT) { CP_WAIT(1); } else { CP_WAIT(0); }
        __syncthreads();
        if (t + 2 < NT) { LOADG(t + 2, (t + 2) % 3); CP_COMMIT(); }

        const uint32_t aB = sb + (t % 3) * HSTG;
        const uint32_t bB = aB + 128 * HROWB;
#pragma unroll
        for (int ks = 0; ks < 2; ++ks) {
            const int kbyte = ks * 32 + lkb;
            uint32_t af[4][4];
#pragma unroll
            for (int mf = 0; mf < 4; ++mf)
                LDSM4(af[mf][0], af[mf][1], af[mf][2], af[mf][3],
                      aB + (wm * 64 + mf * 16 + lr) * HROWB + kbyte);
            uint32_t bfr[2][4];
#pragma unroll
            for (int p = 0; p < 2; ++p)
                LDSM4(bfr[p][0], bfr[p][1], bfr[p][2], bfr[p][3],
                      bB + (wn * 32 + p * 16 + lr) * HROWB + kbyte);
#pragma unroll
            for (int mf = 0; mf < 4; ++mf)
#pragma unroll
                for (int nf = 0; nf < 4; ++nf)
                    mma16816<FP16>(acc[mf][nf], af[mf],
                                   bfr[nf >> 1][nf & 1], bfr[nf >> 1][(nf & 1) + 2]);
        }
    }

    const int rbase = row0 + wm * 64 + (lane >> 2);
    const int cbase = col0 + wn * 32 + 2 * (lane & 3);
#pragma unroll
    for (int nf = 0; nf < 4; ++nf) {
        const int col = cbase + nf * 8;
        if (col >= Nreal) continue;
        const float2 bv = *reinterpret_cast<const float2*>(bias + col);
#pragma unroll
        for (int mf = 0; mf < 4; ++mf) {
            const int r = rbase + mf * 16;
            *reinterpret_cast<float2*>(C + (size_t)r * ldc + col) =
                make_float2(acc[mf][nf][0] + bv.x, acc[mf][nf][1] + bv.y);
            *reinterpret_cast<float2*>(C + (size_t)(r + 8) * ldc + col) =
                make_float2(acc[mf][nf][2] + bv.x, acc[mf][nf][3] + bv.y);
        }
    }
}

// ---------------------------------------------------------------------------
// Conversion kernels
// ---------------------------------------------------------------------------
__global__ void k_split_a(const float* __restrict__ src,
                          __nv_bfloat16* __restrict__ dst, int M)
{
    int i = blockIdx.x * blockDim.x + threadIdx.x;
    int n = M * 512;
    for (; i < n; i += gridDim.x * blockDim.x) {
        int m = i >> 9, j = i & 511;
        float x = src[i];
        __nv_bfloat16 hi = __float2bfloat16(x);
        __nv_bfloat16 lo = __float2bfloat16(x - __bfloat162float(hi));
        __nv_bfloat16* d = dst + (size_t)m * KBF;
        d[j] = hi; d[j + 512] = hi; d[j + 1024] = lo;
    }
}

__global__ void k_split_b(const float* __restrict__ src, int ld,
                          __nv_bfloat16* __restrict__ dst, int Nreal, int Npad)
{
    int i = blockIdx.x * blockDim.x + threadIdx.x;
    int n = Npad * 512;
    for (; i < n; i += gridDim.x * blockDim.x) {
        int r = i >> 9, j = i & 511;
        float x = (r < Nreal) ? src[(size_t)r * ld + j] : 0.f;
        __nv_bfloat16 hi = __float2bfloat16(x);
        __nv_bfloat16 lo = __float2bfloat16(x - __bfloat162float(hi));
        __nv_bfloat16* d = dst + (size_t)r * KBF;
        d[j] = hi; d[j + 512] = lo; d[j + 1024] = hi;
    }
}

// fp16 1-term (W_out)
__global__ void k_split_b16(const float* __restrict__ src, int ld,
                            __half* __restrict__ dst, int Nreal, int Npad)
{
    int i = blockIdx.x * blockDim.x + threadIdx.x;
    int n = Npad * 512;
    for (; i < n; i += gridDim.x * blockDim.x) {
        int r = i >> 9, j = i & 511;
        float x = (r < Nreal) ? src[(size_t)r * ld + j] : 0.f;
        dst[(size_t)r * KH1 + j] = __float2half(x);
    }
}

// ---------------------------------------------------------------------------
// Prep kernels
// ---------------------------------------------------------------------------
__global__ void k_prep(const float* __restrict__ b_ih, const float* __restrict__ b_hh)
{
    int idx = blockIdx.x * blockDim.x + threadIdx.x;
    int stride = gridDim.x * blockDim.x;
    if (idx == 0) g_bar = 0;
    for (int i = idx; i < B*H; i += stride) {
        g_buf[H_OFF + i] = 0.f;
        g_buf[C_OFF + i] = 0.f;
    }
    for (int i = idx; i < B*G4; i += stride)
        g_buf[GH_OFF + i] = 0.f;
    for (int i = idx; i < G4; i += stride)
        g_buf[BS_OFF + i] = b_ih[i] + b_hh[i];
}

__global__ void k_build_xs(const float* __restrict__ features,
                           const int*   __restrict__ captions,
                           const float* __restrict__ embed)
{
    int idx = blockIdx.x * blockDim.x + threadIdx.x;
    int stride = gridDim.x * blockDim.x;
    for (int i = idx; i < TP1*B*E; i += stride) {
        int e  = i & (E - 1);
        int be = i >> 9;
        int b  = be & (B - 1);
        int t  = be >> 7;
        float v;
        if (t == 0) {
            v = features[b*E + e];
        } else {
            int tok = captions[b*T + (t - 1)];
            v = embed[(size_t)tok*E + e];
        }
        g_buf[XS_OFF + i] = v;
    }
}

// ---------------------------------------------------------------------------
// Persistent recurrence kernel
// ---------------------------------------------------------------------------

// device-wide barrier (all blocks resident; counter zeroed by k_prep)
__device__ __forceinline__ void gsync(unsigned& target)
{
    __threadfence();          // release: drain this thread's writes to L2
    __syncthreads();
    if (threadIdx.x == 0) {
        target += GRID_R;
        atomicAdd(&g_bar, 1u);
        while (*(volatile unsigned*)&g_bar < target) { }
        __threadfence();      // acquire + L1D invalidate (CCTL.IVALL)
    }
    __syncthreads();
}

// 32x64 fp32 tile GEMM, K=512, 128 threads; verbatim proven FFMA2 core.
// SUMA: A tile = At (ld 512) + sum of 4 slabs at slab0 + z*SLAB (ld 512).
struct TileSmem {
    float4 As[2][32][8];
    float4 Ws[2][32][16];
};

template<bool SUMA>
__device__ void tile_gemm(float* __restrict__ Ct, int ldc,
                          const float* __restrict__ At, int lda,
                          const float* __restrict__ slab0,
                          const float* __restrict__ Wt, int ldw,
                          TileSmem* sm)
{
    constexpr int NTILE = 16;   // K=512 / BK=32
    const int tid = threadIdx.x;
    const int tn  = tid & 15;   // BN/TN = 16
    const int tm  = tid >> 4;   // BM/TM = 8

    ull acc[2][4];
#pragma unroll
    for (int i = 0; i < 2; ++i)
#pragma unroll
        for (int j = 0; j < 4; ++j) acc[i][j] = 0ULL;

    float4 ra[2], rw[4];

    auto LOADT = [&](int t) {
        const int k0 = t * 32;
#pragma unroll
        for (int i = 0; i < 2; ++i) {
            int idx = tid + i * 128;
            int m = idx >> 3, kq = idx & 7;
            float4 v = *reinterpret_cast<const float4*>(At + (size_t)m*lda + k0 + kq*4);
            if (SUMA) {
#pragma unroll
                for (int z = 0; z < 4; ++z) {
                    float4 s = *reinterpret_cast<const float4*>(
                        slab0 + (size_t)z*SLAB + m*512 + k0 + kq*4);
                    v.x += s.x; v.y += s.y; v.z += s.z; v.w += s.w;
                }
            }
            ra[i] = v;
        }
#pragma unroll
        for (int i = 0; i < 4; ++i) {
            int idx = tid + i * 128;
            int n = idx >> 3, kq = idx & 7;
            rw[i] = *reinterpret_cast<const float4*>(Wt + (size_t)n*ldw + k0 + kq*4);
        }
    };

    auto STORET = [&](int bsel) {
#pragma unroll
        for (int i = 0; i < 2; ++i) {
            int idx = tid + i * 128;
            int m = idx >> 3, kq = idx & 7;
            const float* pv = reinterpret_cast<const float*>(&ra[i]);
#pragma unroll
            for (int r = 0; r < 4; ++r) {
                int k = kq*4 + r;
                int j = (m >> 2) ^ kq;
                reinterpret_cast<float*>(&sm->As[bsel][k][j])[m & 3] = pv[r];
            }
        }
#pragma unroll
        for (int i = 0; i < 4; ++i) {
            int idx = tid + i * 128;
            int n = idx >> 3, kq = idx & 7;
            const float* pv = reinterpret_cast<const float*>(&rw[i]);
#pragma unroll
            for (int r = 0; r < 4; ++r) {
                int k = kq*4 + r;
                int j = (n >> 2) ^ kq;
                reinterpret_cast<float*>(&sm->Ws[bsel][k][j])[n & 3] = pv[r];
            }
        }
    };

    auto COMP = [&](int bsel) {
#pragma unroll
        for (int k = 0; k < 32; ++k) {
            const int s = (k >> 2) & 7;
            ulonglong2 p = *reinterpret_cast<const ulonglong2*>(&sm->As[bsel][k][tm ^ s]);
            ull a0 = p.x, a1 = p.y;
            float4 wv = sm->Ws[bsel][k][tn ^ s];
            ull w0 = dup2(wv.x), w1 = dup2(wv.y), w2 = dup2(wv.z), w3 = dup2(wv.w);
            acc[0][0] = ffma2(a0, w0, acc[0][0]);
            acc[0][1] = ffma2(a0, w1, acc[0][1]);
            acc[0][2] = ffma2(a0, w2, acc[0][2]);
            acc[0][3] = ffma2(a0, w3, acc[0][3]);
            acc[1][0] = ffma2(a1, w0, acc[1][0]);
            acc[1][1] = ffma2(a1, w1, acc[1][1]);
            acc[1][2] = ffma2(a1, w2, acc[1][2]);
            acc[1][3] = ffma2(a1, w3, acc[1][3]);
        }
    };

    LOADT(0);
    STORET(0);
    __syncthreads();
    for (int t = 0; t < NTILE; ++t) {
        if (t + 1 < NTILE) LOADT(t + 1);
        COMP(t & 1);
        if (t + 1 < NTILE) {
            __syncthreads();
            STORET((t + 1) & 1);
            __syncthreads();
        }
    }

    const int cc = tn * 4;
#pragma unroll
    for (int i = 0; i < 2; ++i) {
        float2 u[4];
#pragma unroll
        for (int j = 0; j < 4; ++j) u[j] = unpk(acc[i][j]);
#pragma unroll
        for (int rr = 0; rr < 2; ++rr) {
            int r = tm*4 + 2*i + rr;
            *reinterpret_cast<float4*>(Ct + (size_t)r*ldc + cc) = make_float4(
                rr == 0 ? u[0].x : u[0].y, rr == 0 ? u[1].x : u[1].y,
                rr == 0 ? u[2].x : u[2].y, rr == 0 ? u[3].x : u[3].y);
        }
    }
    __syncthreads();
}

__global__ void __launch_bounds__(128)
k_recur(const float* __restrict__ cnn,
        const float* __restrict__ W_attn,   // [A][E+H]
        const float* __restrict__ W_hh,     // [G4][H]
        const float* __restrict__ W_ih,     // [G4][E]
        const float* __restrict__ W_attd,   // [E][E+A]
        __half* __restrict__ hid16)
{
    __shared__ TileSmem tsm;
    __shared__ float red[128];

    float* xs   = g_buf + XS_OFF;
    float* pan  = g_buf + PAN_OFF;
    float* pad  = g_buf + PAD_OFF;
    float* h    = g_buf + H_OFF;
    float* c    = g_buf + C_OFF;
    float* att  = g_buf + ATT_OFF;
    float* sc   = g_buf + SC_OFF;
    float* gh   = g_buf + GH_OFF;
    float* gx   = g_buf + GX_OFF;
    float* slD  = g_buf + SLD_OFF;
    float* bsum = g_buf + BS_OFF;

    const int bid = blockIdx.x;
    const int tid = threadIdx.x;
    unsigned target = 0;

    auto lstm = [&](int t) {
        for (int idx = bid * 128 + tid; idx < B * H; idx += GRID_R * 128) {
            int b = idx >> 9, j = idx & 511;
            const float* ghp = gh + (size_t)b * G4;
            const float* gxp = gx + (size_t)b * G4;
            float gi = bsum[j]        + ghp[j]        + gxp[j];
            float gf = bsum[j + 512]  + ghp[j + 512]  + gxp[j + 512];
            float gg = bsum[j + 1024] + ghp[j + 1024] + gxp[j + 1024];
            float go = bsum[j + 1536] + ghp[j + 1536] + gxp[j + 1536];
            float ig = 1.f / (1.f + expf(-gi));
            float fg = 1.f / (1.f + expf(-gf));
            float gt = tanhf(gg);
            float og = 1.f / (1.f + expf(-go));
            float cn = fg * c[idx] + ig * gt;
            float hn = og * tanhf(cn);
            c[idx] = cn;
            h[idx] = hn;
            hid16[((size_t)t * B + b) * KH1 + j] = __float2half(hn);
        }
    };

    // step 0: gates_x = xs0 @ W_ih^T (gh is zeroed by prep)
    if (bid < 128) {
        int rb = bid >> 5, cb = bid & 31;
        tile_gemm<false>(gx + (size_t)rb*32*G4 + cb*64, G4,
                         xs + (size_t)rb*32*E, E, nullptr,
                         W_ih + (size_t)(cb*64)*E, E, &tsm);
    }
    gsync(target);
    lstm(0);
    gsync(target);

    for (int t = 1; t <= T; ++t) {
        // PH_A: sc = h @ WattnH^T  and  gh = h @ W_hh^T
        if (bid < 256) {
            int u = bid & 127;
            int rb = u >> 5, cb = u & 31;
            if (bid < 128) {
                tile_gemm<false>(sc + (size_t)rb*32*A + cb*64, A,
                                 h + (size_t)rb*32*H, H, nullptr,
                                 W_attn + (size_t)(cb*64)*(E+H) + E, E+H, &tsm);
            } else {
                tile_gemm<false>(gh + (size_t)rb*32*G4 + cb*64, G4,
                                 h + (size_t)rb*32*H, H, nullptr,
                                 W_hh + (size_t)(cb*64)*H, H, &tsm);
            }
        }
        gsync(target);

        // PH_B: softmax(pan[t] + sc) * cnn -> att (one block per row)
        if (bid < 128) {
            const float* pr = pan + (size_t)t*B*A + (size_t)bid*A;
            const float* sr = sc + (size_t)bid*A;
            float v[16];
            float mx = -1e30f;
#pragma unroll
            for (int i = 0; i < 16; ++i) {
                v[i] = pr[tid + 128*i] + sr[tid + 128*i];
                mx = fmaxf(mx, v[i]);
            }
            red[tid] = mx; __syncthreads();
            for (int off = 64; off > 0; off >>= 1) {
                if (tid < off) red[tid] = fmaxf(red[tid], red[tid + off]);
                __syncthreads();
            }
            mx = red[0]; __syncthreads();
            float sum = 0.f;
#pragma unroll
            for (int i = 0; i < 16; ++i) { v[i] = expf(v[i] - mx); sum += v[i]; }
            red[tid] = sum; __syncthreads();
            for (int off = 64; off > 0; off >>= 1) {
                if (tid < off) red[tid] += red[tid + off];
                __syncthreads();
            }
            float inv = 1.f / red[0];
            const float* cb = cnn + (size_t)bid*A;
            float* ab = att + (size_t)bid*A;
#pragma unroll
            for (int i = 0; i < 16; ++i)
                ab[tid + 128*i] = cb[tid + 128*i] * v[i] * inv;
            __syncthreads();
        }
        gsync(target);

        // PH_C: attd split-K4: slD[z] = att[:, z*512:+512] @ WattdA[:, z*512:+512]^T
        if (bid < 128) {
            int z = bid >> 5, r2 = bid & 31;
            int rb = r2 >> 3, cb = r2 & 7;
            tile_gemm<false>(slD + (size_t)z*SLAB + (size_t)rb*32*E + cb*64, E,
                             att + (size_t)rb*32*A + z*512, A, nullptr,
                             W_attd + (size_t)(cb*64)*(E+A) + E + z*512, E+A, &tsm);
        }
        gsync(target);

        // PH_D: gx = x2 @ W_ih^T with x2 = pad[t] + sum(slD) fused in A-loader
        if (bid < 128) {
            int rb = bid >> 5, cb = bid & 31;
            tile_gemm<true>(gx + (size_t)rb*32*G4 + cb*64, G4,
                            pad + (size_t)t*B*E + (size_t)rb*32*E, E,
                            slD + (size_t)rb*32*E,
                            W_ih + (size_t)(cb*64)*E, E, &tsm);
        }
        gsync(target);

        // PH_F: LSTM pointwise
        lstm(t);
        gsync(target);
    }
}

// ---------------------------------------------------------------------------
// Host launch sequence (graph-capturable: kernel launches only)
// ---------------------------------------------------------------------------
extern "C" void kernel_launch(void* const* d_in, const int* in_sizes, int n_in,
                              void* d_out, int out_size)
{
    const float* features = (const float*)d_in[0];
    const float* cnn      = (const float*)d_in[1];
    const int*   captions = (const int*)  d_in[2];
    /* d_in[3] = lengths (unused: all T+1) */
    const float* embed    = (const float*)d_in[4];
    const float* W_ih     = (const float*)d_in[5];
    const float* W_hh     = (const float*)d_in[6];
    const float* b_ih     = (const float*)d_in[7];
    const float* b_hh     = (const float*)d_in[8];
    const float* W_attn   = (const float*)d_in[9];
    const float* b_attn   = (const float*)d_in[10];
    const float* W_attd   = (const float*)d_in[11];
    const float* b_attd   = (const float*)d_in[12];
    const float* W_out    = (const float*)d_in[13];
    const float* b_out    = (const float*)d_in[14];
    float* out = (float*)d_out;

    float* buf = nullptr;
    cudaGetSymbolAddress((void**)&buf, g_buf);
    __nv_bfloat16 *xs_bf, *wattn_bf, *wattd_bf;
    __half *hid_h, *wout_h;
    cudaGetSymbolAddress((void**)&xs_bf,    g_xs_bf);
    cudaGetSymbolAddress((void**)&wattn_bf, g_wattn_bf);
    cudaGetSymbolAddress((void**)&wattd_bf, g_wattd_bf);
    cudaGetSymbolAddress((void**)&hid_h,    g_hid_h);
    cudaGetSymbolAddress((void**)&wout_h,   g_wout_h);

    cudaFuncSetAttribute(hmma_gemm<KBF, false>,
                         cudaFuncAttributeMaxDynamicSharedMemorySize, HSMEM);
    cudaFuncSetAttribute(hmma_gemm<KH1, true>,
                         cudaFuncAttributeMaxDynamicSharedMemorySize, HSMEM);

    float* xs  = buf + XS_OFF;
    float* pan = buf + PAN_OFF;
    float* pad = buf + PAD_OFF;

    // prep
    k_prep<<<1024, 256>>>(b_ih, b_hh);
    k_build_xs<<<2048, 256>>>(features, captions, embed);

    // conversions
    k_split_a<<<4096, 256>>>(xs, xs_bf, MALL);
    k_split_b<<<2048, 256>>>(W_attn, E + H, wattn_bf, A, A);
    k_split_b<<<1024, 256>>>(W_attd, E + A, wattd_bf, E, E);
    k_split_b16<<<4096, 256>>>(W_out, H, wout_h, V, VPAD);

    // pan[t] = x_t @ W_attn[:, :E]^T + b_attn  (bf16 3-term)
    hmma_gemm<KBF, false><<<dim3(A / 128, MALL / 128), 256, HSMEM>>>(
        pan, A, A, (const uint16_t*)xs_bf, (const uint16_t*)wattn_bf, b_attn);
    // pad[t] = x_t @ W_attd[:, :E]^T + b_attd  (bf16 3-term)
    hmma_gemm<KBF, false><<<dim3(E / 128, MALL / 128), 256, HSMEM>>>(
        pad, E, E, (const uint16_t*)xs_bf, (const uint16_t*)wattd_bf, b_attd);

    // entire recurrence in one persistent kernel
    k_recur<<<GRID_R, 128>>>(cnn, W_attn, W_hh, W_ih, W_attd, hid_h);

    // logits = hidden @ W_out^T + b_out  (fp16 1-term, K=512)
    hmma_gemm<KH1, true><<<dim3(VPAD / 128, MALL / 128), 256, HSMEM>>>(
        out, V, V, (const uint16_t*)hid_h, (const uint16_t*)wout_h, b_out);
}

// round 8
// speedup vs baseline: 1.1828x; 1.1828x over previous
#include <cuda_runtime.h>
#include <cuda_bf16.h>
#include <cuda_fp16.h>
#include <math.h>
#include <stdint.h>

// ---------------------------------------------------------------------------
// Problem constants
// ---------------------------------------------------------------------------
namespace {
constexpr int B   = 128;
constexpr int T   = 31;
constexpr int TP1 = 32;     // T+1
constexpr int E   = 512;
constexpr int H   = 512;
constexpr int V   = 10000;
constexpr int A   = 2048;
constexpr int G4  = 2048;   // 4*H
constexpr int NC  = 4096;   // comb GEMM cols: [scores | gates_h]
constexpr int MALL = TP1 * B;   // 4096
constexpr int VPAD = 10240;     // 80 * 128
constexpr int KBF  = 1536;      // 3 * 512 split-bf16 K (pan/pad)
constexpr int KH1  = 512;       // 1-term fp16 K (logits)

// scratch layout (floats) inside one __device__ buffer
constexpr size_t XS_OFF   = 0;                              // [TP1][B][E]
constexpr size_t PAN_OFF  = XS_OFF  + (size_t)TP1*B*E;      // [TP1][B][A]
constexpr size_t PAD_OFF  = PAN_OFF + (size_t)TP1*B*A;      // [TP1][B][E]
constexpr size_t H_OFF    = PAD_OFF + (size_t)TP1*B*E;      // [B][H]
constexpr size_t C_OFF    = H_OFF   + (size_t)B*H;          // [B][H]
constexpr size_t ATT_OFF  = C_OFF   + (size_t)B*H;          // [B][A]
constexpr size_t SLC_OFF  = ATT_OFF + (size_t)B*A;          // [4][B][NC]
constexpr size_t SLD_OFF  = SLC_OFF + (size_t)4*B*NC;       // [8][B][E]
constexpr size_t SLG_OFF  = SLD_OFF + (size_t)8*B*E;        // [4][B][G4]
constexpr size_t WC_OFF   = SLG_OFF + (size_t)4*B*G4;       // [NC][512] Wcomb
constexpr size_t BS_OFF   = WC_OFF  + (size_t)NC*512;       // [G4]
constexpr size_t BUF_TOTAL = BS_OFF + (size_t)G4;

constexpr int SLABD = B * E;     // slD slab stride (65536)
}

__device__ float g_buf[BUF_TOTAL];

// bf16 split operand buffers (pan/pad: 3-term)
__device__ __nv_bfloat16 g_xs_bf [(size_t)MALL * KBF];
__device__ __nv_bfloat16 g_wattn_bf[(size_t)A * KBF];
__device__ __nv_bfloat16 g_wattd_bf[(size_t)E * KBF];
// fp16 1-term buffers (logits)
__device__ __half g_hid_h [(size_t)MALL * KH1];
__device__ __half g_wout_h[(size_t)VPAD * KH1];

// ---------------------------------------------------------------------------
// Packed f32x2 FMA helpers
// ---------------------------------------------------------------------------
typedef unsigned long long ull;

__device__ __forceinline__ ull ffma2(ull a, ull b, ull c) {
    ull d;
    asm("fma.rn.f32x2 %0, %1, %2, %3;" : "=l"(d) : "l"(a), "l"(b), "l"(c));
    return d;
}
__device__ __forceinline__ ull dup2(float x) {
    ull d;
    asm("mov.b64 %0, {%1, %1};" : "=l"(d) : "f"(x));
    return d;
}
__device__ __forceinline__ float2 unpk(ull v) {
    float2 r;
    asm("mov.b64 {%0, %1}, %2;" : "=f"(r.x), "=f"(r.y) : "l"(v));
    return r;
}

// ---------------------------------------------------------------------------
// HMMA helpers (sm_80+ PTX)
// ---------------------------------------------------------------------------
__device__ __forceinline__ uint32_t smem_u32(const void* p) {
    uint32_t a;
    asm("{ .reg .u64 t; cvta.to.shared.u64 t, %1; cvt.u32.u64 %0, t; }"
        : "=r"(a) : "l"(p));
    return a;
}
__device__ __forceinline__ void cpa16(uint32_t s, const void* g) {
    asm volatile("cp.async.cg.shared.global [%0], [%1], 16;"
                 :: "r"(s), "l"(g));
}
#define CP_COMMIT() asm volatile("cp.async.commit_group;" ::: "memory")
#define CP_WAIT(N)  asm volatile("cp.async.wait_group %0;" :: "n"(N) : "memory")

#define LDSM4(R0, R1, R2, R3, ADDR) \
    asm volatile("ldmatrix.sync.aligned.m8n8.x4.shared.b16 {%0,%1,%2,%3}, [%4];" \
        : "=r"(R0), "=r"(R1), "=r"(R2), "=r"(R3) : "r"(ADDR))

template<bool FP16>
__device__ __forceinline__ void mma16816(float* d, const uint32_t* a,
                                         uint32_t b0, uint32_t b1) {
    if constexpr (FP16) {
        asm volatile(
            "mma.sync.aligned.m16n8k16.row.col.f32.f16.f16.f32 "
            "{%0,%1,%2,%3}, {%4,%5,%6,%7}, {%8,%9}, {%0,%1,%2,%3};"
            : "+f"(d[0]), "+f"(d[1]), "+f"(d[2]), "+f"(d[3])
            : "r"(a[0]), "r"(a[1]), "r"(a[2]), "r"(a[3]), "r"(b0), "r"(b1));
    } else {
        asm volatile(
            "mma.sync.aligned.m16n8k16.row.col.f32.bf16.bf16.f32 "
            "{%0,%1,%2,%3}, {%4,%5,%6,%7}, {%8,%9}, {%0,%1,%2,%3};"
            : "+f"(d[0]), "+f"(d[1]), "+f"(d[2]), "+f"(d[3])
            : "r"(a[0]), "r"(a[1]), "r"(a[2]), "r"(a[3]), "r"(b0), "r"(b1));
    }
}

namespace {
constexpr int HBK   = 32;
constexpr int HROWB = 80;            // 32 elems * 2B + 16B pad
constexpr int HSTG  = 256 * HROWB;   // 20480 B per stage
constexpr int HSMEM = 3 * HSTG;      // 61440 B
}

template<int KTOT, bool FP16>
__global__ void __launch_bounds__(256, 2)
hmma_gemm(float* __restrict__ C, int ldc, int Nreal,
          const uint16_t* __restrict__ Abf,
          const uint16_t* __restrict__ Bbf,
          const float* __restrict__ bias)
{
    constexpr int NT = KTOT / HBK;
    extern __shared__ __align__(16) char sm[];
    const uint32_t sb = smem_u32(sm);

    const int tid  = threadIdx.x;
    const int wid  = tid >> 5;
    const int lane = tid & 31;
    const int wm   = wid & 1;
    const int wn   = wid >> 1;
    const int row0 = blockIdx.y * 128;
    const int col0 = blockIdx.x * 128;

    const int qr0 = (tid)       >> 2, qc0 = (tid)       & 3;
    const int qr1 = (tid + 256) >> 2, qc1 = (tid + 256) & 3;

    auto LOADG = [&](int t, int stg) {
        const int k0 = t * HBK;
        const uint32_t sa  = sb + stg * HSTG;
        const uint32_t sbm = sa + 128 * HROWB;
        cpa16(sa  + qr0 * HROWB + qc0 * 16,
              Abf + (size_t)(row0 + qr0) * KTOT + k0 + qc0 * 8);
        cpa16(sa  + qr1 * HROWB + qc1 * 16,
              Abf + (size_t)(row0 + qr1) * KTOT + k0 + qc1 * 8);
        cpa16(sbm + qr0 * HROWB + qc0 * 16,
              Bbf + (size_t)(col0 + qr0) * KTOT + k0 + qc0 * 8);
        cpa16(sbm + qr1 * HROWB + qc1 * 16,
              Bbf + (size_t)(col0 + qr1) * KTOT + k0 + qc1 * 8);
    };

    float acc[4][4][4];
#pragma unroll
    for (int i = 0; i < 4; ++i)
#pragma unroll
        for (int j = 0; j < 4; ++j)
#pragma unroll
            for (int q = 0; q < 4; ++q) acc[i][j][q] = 0.f;

    const int lr  = lane & 15;
    const int lkb = (lane >> 4) * 16;

    LOADG(0, 0); CP_COMMIT();
    LOADG(1, 1); CP_COMMIT();

    for (int t = 0; t < NT; ++t) {
        if (t + 1 < NT) { CP_WAIT(1); } else { CP_WAIT(0); }
        __syncthreads();
        if (t + 2 < NT) { LOADG(t + 2, (t + 2) % 3); CP_COMMIT(); }

        const uint32_t aB = sb + (t % 3) * HSTG;
        const uint32_t bB = aB + 128 * HROWB;
#pragma unroll
        for (int ks = 0; ks < 2; ++ks) {
            const int kbyte = ks * 32 + lkb;
            uint32_t af[4][4];
#pragma unroll
            for (int mf = 0; mf < 4; ++mf)
                LDSM4(af[mf][0], af[mf][1], af[mf][2], af[mf][3],
                      aB + (wm * 64 + mf * 16 + lr) * HROWB + kbyte);
            uint32_t bfr[2][4];
#pragma unroll
            for (int p = 0; p < 2; ++p)
                LDSM4(bfr[p][0], bfr[p][1], bfr[p][2], bfr[p][3],
                      bB + (wn * 32 + p * 16 + lr) * HROWB + kbyte);
#pragma unroll
            for (int mf = 0; mf < 4; ++mf)
#pragma unroll
                for (int nf = 0; nf < 4; ++nf)
                    mma16816<FP16>(acc[mf][nf], af[mf],
                                   bfr[nf >> 1][nf & 1], bfr[nf >> 1][(nf & 1) + 2]);
        }
    }

    const int rbase = row0 + wm * 64 + (lane >> 2);
    const int cbase = col0 + wn * 32 + 2 * (lane & 3);
#pragma unroll
    for (int nf = 0; nf < 4; ++nf) {
        const int col = cbase + nf * 8;
        if (col >= Nreal) continue;
        const float2 bv = *reinterpret_cast<const float2*>(bias + col);
#pragma unroll
        for (int mf = 0; mf < 4; ++mf) {
            const int r = rbase + mf * 16;
            *reinterpret_cast<float2*>(C + (size_t)r * ldc + col) =
                make_float2(acc[mf][nf][0] + bv.x, acc[mf][nf][1] + bv.y);
            *reinterpret_cast<float2*>(C + (size_t)(r + 8) * ldc + col) =
                make_float2(acc[mf][nf][2] + bv.x, acc[mf][nf][3] + bv.y);
        }
    }
}

// ---------------------------------------------------------------------------
// Conversion kernels
// ---------------------------------------------------------------------------
__global__ void k_split_a(const float* __restrict__ src,
                          __nv_bfloat16* __restrict__ dst, int M)
{
    int i = blockIdx.x * blockDim.x + threadIdx.x;
    int n = M * 512;
    for (; i < n; i += gridDim.x * blockDim.x) {
        int m = i >> 9, j = i & 511;
        float x = src[i];
        __nv_bfloat16 hi = __float2bfloat16(x);
        __nv_bfloat16 lo = __float2bfloat16(x - __bfloat162float(hi));
        __nv_bfloat16* d = dst + (size_t)m * KBF;
        d[j] = hi; d[j + 512] = hi; d[j + 1024] = lo;
    }
}

__global__ void k_split_b(const float* __restrict__ src, int ld,
                          __nv_bfloat16* __restrict__ dst, int Nreal, int Npad)
{
    int i = blockIdx.x * blockDim.x + threadIdx.x;
    int n = Npad * 512;
    for (; i < n; i += gridDim.x * blockDim.x) {
        int r = i >> 9, j = i & 511;
        float x = (r < Nreal) ? src[(size_t)r * ld + j] : 0.f;
        __nv_bfloat16 hi = __float2bfloat16(x);
        __nv_bfloat16 lo = __float2bfloat16(x - __bfloat162float(hi));
        __nv_bfloat16* d = dst + (size_t)r * KBF;
        d[j] = hi; d[j + 512] = lo; d[j + 1024] = hi;
    }
}

// fp16 1-term (W_out)
__global__ void k_split_b16(const float* __restrict__ src, int ld,
                            __half* __restrict__ dst, int Nreal, int Npad)
{
    int i = blockIdx.x * blockDim.x + threadIdx.x;
    int n = Npad * 512;
    for (; i < n; i += gridDim.x * blockDim.x) {
        int r = i >> 9, j = i & 511;
        float x = (r < Nreal) ? src[(size_t)r * ld + j] : 0.f;
        dst[(size_t)r * KH1 + j] = __float2half(x);
    }
}

// ---------------------------------------------------------------------------
// Single-input pipelined fp32 SGEMM (recurrent path), split-K via gridDim.z.
// NSUM > 0: A tile = A[...] + sum of NSUM slabs (slab row length = lda).
// Proven FFMA2 core; BK=32; K, KC multiples of BK.
// ---------------------------------------------------------------------------
template<int BM, int BN, int BK, int TM, int NSUM>
__global__ void __launch_bounds__((BM/TM)*(BN/4))
sgemm_pipe(float* __restrict__ C, int ldc,
           const float* __restrict__ Ab, int lda,
           const float* __restrict__ slab, int slabstride,
           const float* __restrict__ W,  int ldw,
           int M, int N, int K, int KC)
{
    constexpr int TN = 4;
    constexpr int THREADS = (BM/TM)*(BN/TN);
    constexpr int BMq = BM/4, BNq = BN/4, BKq = BK/4;
    constexpr int NA = (BM*BKq)/THREADS;
    constexpr int NW = (BN*BKq)/THREADS;

    __shared__ float4 As[2][BK][BMq];
    __shared__ float4 Ws[2][BK][BNq];

    const int tid  = threadIdx.x;
    const int tn   = tid % (BN/TN);
    const int tm   = tid / (BN/TN);
    const int row0 = blockIdx.y * BM;
    const int col0 = blockIdx.x * BN;
    const int kbeg = blockIdx.z * KC;
    const int kend = (kbeg + KC < K) ? (kbeg + KC) : K;
    const int ntile = (kend - kbeg) / BK;
    float* Cz = C + (size_t)blockIdx.z * M * N;

    ull acc[TM/2][TN];
#pragma unroll
    for (int i = 0; i < TM/2; ++i)
#pragma unroll
        for (int j = 0; j < TN; ++j) acc[i][j] = 0ULL;

    float4 ra[NA], rw[NW];

    auto LOADT = [&](int t) {
        const int k0 = kbeg + t * BK;
#pragma unroll
        for (int i = 0; i < NA; ++i) {
            int idx = tid + i * THREADS;
            int m = idx / BKq, kq = idx % BKq;
            int gm = row0 + m;
            float4 v = *reinterpret_cast<const float4*>(
                Ab + (size_t)gm*lda + k0 + kq*4);
            if (NSUM > 0) {
#pragma unroll
                for (int z = 0; z < NSUM; ++z) {
                    float4 s = *reinterpret_cast<const float4*>(
                        slab + (size_t)z*slabstride + (size_t)gm*lda + k0 + kq*4);
                    v.x += s.x; v.y += s.y; v.z += s.z; v.w += s.w;
                }
            }
            ra[i] = v;
        }
#pragma unroll
        for (int i = 0; i < NW; ++i) {
            int idx = tid + i * THREADS;
            int n = idx / BKq, kq = idx % BKq;
            int gn = col0 + n;
            rw[i] = *reinterpret_cast<const float4*>(
                W + (size_t)gn*ldw + k0 + kq*4);
        }
    };

    auto STORET = [&](int bsel) {
#pragma unroll
        for (int i = 0; i < NA; ++i) {
            int idx = tid + i * THREADS;
            int m = idx / BKq, kq = idx % BKq;
            const float* pv = reinterpret_cast<const float*>(&ra[i]);
#pragma unroll
            for (int r = 0; r < 4; ++r) {
                int k = kq*4 + r;
                int j = (m >> 2) ^ kq;
                reinterpret_cast<float*>(&As[bsel][k][j])[m & 3] = pv[r];
            }
        }
#pragma unroll
        for (int i = 0; i < NW; ++i) {
            int idx = tid + i * THREADS;
            int n = idx / BKq, kq = idx % BKq;
            const float* pv = reinterpret_cast<const float*>(&rw[i]);
#pragma unroll
            for (int r = 0; r < 4; ++r) {
                int k = kq*4 + r;
                int j = (n >> 2) ^ kq;
                reinterpret_cast<float*>(&Ws[bsel][k][j])[n & 3] = pv[r];
            }
        }
    };

    auto COMP = [&](int bsel) {
#pragma unroll
        for (int k = 0; k < BK; ++k) {
            const int s = (k >> 2) & 7;
            ull a2[TM/2];
#pragma unroll
            for (int q = 0; q < TM/4; ++q) {
                ulonglong2 p = *reinterpret_cast<const ulonglong2*>(
                    &As[bsel][k][(tm*(TM/4) + q) ^ s]);
                a2[2*q]   = p.x;
                a2[2*q+1] = p.y;
            }
            float4 wv = Ws[bsel][k][tn ^ s];
            ull w0 = dup2(wv.x), w1 = dup2(wv.y), w2 = dup2(wv.z), w3 = dup2(wv.w);
#pragma unroll
            for (int i = 0; i < TM/2; ++i) {
                acc[i][0] = ffma2(a2[i], w0, acc[i][0]);
                acc[i][1] = ffma2(a2[i], w1, acc[i][1]);
                acc[i][2] = ffma2(a2[i], w2, acc[i][2]);
                acc[i][3] = ffma2(a2[i], w3, acc[i][3]);
            }
        }
    };

    if (ntile > 0) {
        LOADT(0);
        STORET(0);
        __syncthreads();
        for (int t = 0; t < ntile; ++t) {
            if (t + 1 < ntile) LOADT(t + 1);
            COMP(t & 1);
            if (t + 1 < ntile) {
                __syncthreads();
                STORET((t + 1) & 1);
                __syncthreads();
            }
        }
    }

    const int cc = col0 + tn*TN;
#pragma unroll
    for (int i = 0; i < TM/2; ++i) {
        float2 u[TN];
#pragma unroll
        for (int j = 0; j < TN; ++j) u[j] = unpk(acc[i][j]);
#pragma unroll
        for (int rr = 0; rr < 2; ++rr) {
            int r = row0 + tm*TM + 2*i + rr;
            float* cp = Cz + (size_t)r*ldc + cc;
            *reinterpret_cast<float4*>(cp) = make_float4(
                rr == 0 ? u[0].x : u[0].y, rr == 0 ? u[1].x : u[1].y,
                rr == 0 ? u[2].x : u[2].y, rr == 0 ? u[3].x : u[3].y);
        }
    }
}

// ---------------------------------------------------------------------------
// Prep kernels
// ---------------------------------------------------------------------------
__global__ void k_prep(const float* __restrict__ b_ih, const float* __restrict__ b_hh,
                       const float* __restrict__ W_attn, const float* __restrict__ W_hh)
{
    int idx = blockIdx.x * blockDim.x + threadIdx.x;
    int stride = gridDim.x * blockDim.x;
    for (int i = idx; i < B*H; i += stride) {
        g_buf[H_OFF + i] = 0.f;
        g_buf[C_OFF + i] = 0.f;
    }
    for (int i = idx; i < 4*B*NC; i += stride)
        g_buf[SLC_OFF + i] = 0.f;
    for (int i = idx; i < G4; i += stride)
        g_buf[BS_OFF + i] = b_ih[i] + b_hh[i];
    // Wcomb[4096][512]: rows 0..2047 = W_attn[:, E:], rows 2048.. = W_hh
    for (int i = idx; i < NC*512; i += stride) {
        int r = i >> 9, k = i & 511;
        g_buf[WC_OFF + i] = (r < A) ? W_attn[(size_t)r*(E+H) + E + k]
                                    : W_hh[(size_t)(r - A)*H + k];
    }
}

__global__ void k_build_xs(const float* __restrict__ features,
                           const int*   __restrict__ captions,
                           const float* __restrict__ embed)
{
    int idx = blockIdx.x * blockDim.x + threadIdx.x;
    int stride = gridDim.x * blockDim.x;
    for (int i = idx; i < TP1*B*E; i += stride) {
        int e  = i & (E - 1);
        int be = i >> 9;
        int b  = be & (B - 1);
        int t  = be >> 7;
        float v;
        if (t == 0) {
            v = features[b*E + e];
        } else {
            int tok = captions[b*T + (t - 1)];
            v = embed[(size_t)tok*E + e];
        }
        g_buf[XS_OFF + i] = v;
    }
}

// ---------------------------------------------------------------------------
// softmax(pan[t] + 4 comb slabs cols[0:A]) * cnn -> att
// ---------------------------------------------------------------------------
__global__ void __launch_bounds__(256)
k_softmax_att(const float* __restrict__ pre,
              const float* __restrict__ slc,
              const float* __restrict__ cnn,
              float* __restrict__ att)
{
    int b = blockIdx.x;
    int t = threadIdx.x;
    const size_t o0 = (size_t)b*A;
    const float* s0 = slc + (size_t)b*NC;
    const size_t SS = (size_t)B*NC;
    float v[8];
    float mx = -1e30f;
#pragma unroll
    for (int i = 0; i < 8; ++i) {
        int j = t + 256*i;
        float s = pre[o0 + j] + s0[j] + s0[j + SS] + s0[j + 2*SS] + s0[j + 3*SS];
        v[i] = s;
        mx = fmaxf(mx, s);
    }
    __shared__ float red[256];
    red[t] = mx; __syncthreads();
    for (int off = 128; off > 0; off >>= 1) {
        if (t < off) red[t] = fmaxf(red[t], red[t + off]);
        __syncthreads();
    }
    mx = red[0]; __syncthreads();

    float sum = 0.f;
#pragma unroll
    for (int i = 0; i < 8; ++i) {
        v[i] = expf(v[i] - mx);
        sum += v[i];
    }
    red[t] = sum; __syncthreads();
    for (int off = 128; off > 0; off >>= 1) {
        if (t < off) red[t] += red[t + off];
        __syncthreads();
    }
    float inv = 1.f / red[0];

    const float* cb = cnn + o0;
    float* ab = att + o0;
#pragma unroll
    for (int i = 0; i < 8; ++i)
        ab[t + 256*i] = cb[t + 256*i] * v[i] * inv;
}

// LSTM pointwise: gates = bsum + 4 comb slabs (cols A..) + 4 gate_x slabs.
// h written fp32 (next-step GEMM input) and fp16 (logits operand).
__global__ void __launch_bounds__(256)
k_lstm_red(const float* __restrict__ slc,
           const float* __restrict__ slg,
           const float* __restrict__ bsum,
           float* __restrict__ h, float* __restrict__ c,
           __half* __restrict__ hid16)
{
    int idx = blockIdx.x * blockDim.x + threadIdx.x;
    if (idx >= B*H) return;
    int b = idx >> 9;
    int j = idx & 511;
    float gi = bsum[j], gf = bsum[j + 512], gg = bsum[j + 1024], go = bsum[j + 1536];
#pragma unroll
    for (int z = 0; z < 4; ++z) {
        const float* gc = slc + (size_t)z*B*NC + (size_t)b*NC + A;
        const float* gx = slg + (size_t)z*B*G4 + (size_t)b*G4;
        gi += gc[j]        + gx[j];
        gf += gc[j + 512]  + gx[j + 512];
        gg += gc[j + 1024] + gx[j + 1024];
        go += gc[j + 1536] + gx[j + 1536];
    }
    float ig = 1.f / (1.f + expf(-gi));
    float fg = 1.f / (1.f + expf(-gf));
    float gt = tanhf(gg);
    float og = 1.f / (1.f + expf(-go));
    float cn = fg * c[idx] + ig * gt;
    float hn = og * tanhf(cn);
    c[idx] = cn;
    h[idx] = hn;
    hid16[(size_t)b * KH1 + j] = __float2half(hn);
}

// ---------------------------------------------------------------------------
// Host launch sequence (graph-capturable: kernel launches only)
// ---------------------------------------------------------------------------
extern "C" void kernel_launch(void* const* d_in, const int* in_sizes, int n_in,
                              void* d_out, int out_size)
{
    const float* features = (const float*)d_in[0];
    const float* cnn      = (const float*)d_in[1];
    const int*   captions = (const int*)  d_in[2];
    /* d_in[3] = lengths (unused: all T+1) */
    const float* embed    = (const float*)d_in[4];
    const float* W_ih     = (const float*)d_in[5];
    const float* W_hh     = (const float*)d_in[6];
    const float* b_ih     = (const float*)d_in[7];
    const float* b_hh     = (const float*)d_in[8];
    const float* W_attn   = (const float*)d_in[9];
    const float* b_attn   = (const float*)d_in[10];
    const float* W_attd   = (const float*)d_in[11];
    const float* b_attd   = (const float*)d_in[12];
    const float* W_out    = (const float*)d_in[13];
    const float* b_out    = (const float*)d_in[14];
    float* out = (float*)d_out;

    float* buf = nullptr;
    cudaGetSymbolAddress((void**)&buf, g_buf);
    __nv_bfloat16 *xs_bf, *wattn_bf, *wattd_bf;
    __half *hid_h, *wout_h;
    cudaGetSymbolAddress((void**)&xs_bf,    g_xs_bf);
    cudaGetSymbolAddress((void**)&wattn_bf, g_wattn_bf);
    cudaGetSymbolAddress((void**)&wattd_bf, g_wattd_bf);
    cudaGetSymbolAddress((void**)&hid_h,    g_hid_h);
    cudaGetSymbolAddress((void**)&wout_h,   g_wout_h);

    cudaFuncSetAttribute(hmma_gemm<KBF, false>,
                         cudaFuncAttributeMaxDynamicSharedMemorySize, HSMEM);
    cudaFuncSetAttribute(hmma_gemm<KH1, true>,
                         cudaFuncAttributeMaxDynamicSharedMemorySize, HSMEM);

    float* xs    = buf + XS_OFF;
    float* pan   = buf + PAN_OFF;
    float* pad   = buf + PAD_OFF;
    float* hbuf  = buf + H_OFF;
    float* cbuf  = buf + C_OFF;
    float* att   = buf + ATT_OFF;
    float* slC   = buf + SLC_OFF;
    float* slD   = buf + SLD_OFF;
    float* slG   = buf + SLG_OFF;
    float* Wcomb = buf + WC_OFF;
    float* bsum  = buf + BS_OFF;

    // prep
    k_prep<<<2048, 256>>>(b_ih, b_hh, W_attn, W_hh);
    k_build_xs<<<2048, 256>>>(features, captions, embed);

    // conversions
    k_split_a<<<4096, 256>>>(xs, xs_bf, MALL);
    k_split_b<<<2048, 256>>>(W_attn, E + H, wattn_bf, A, A);
    k_split_b<<<1024, 256>>>(W_attd, E + A, wattd_bf, E, E);
    k_split_b16<<<4096, 256>>>(W_out, H, wout_h, V, VPAD);

    // pan[t] = x_t @ W_attn[:, :E]^T + b_attn  (bf16 3-term)
    hmma_gemm<KBF, false><<<dim3(A / 128, MALL / 128), 256, HSMEM>>>(
        pan, A, A, (const uint16_t*)xs_bf, (const uint16_t*)wattn_bf, b_attn);
    // pad[t] = x_t @ W_attd[:, :E]^T + b_attd  (bf16 3-term)
    hmma_gemm<KBF, false><<<dim3(E / 128, MALL / 128), 256, HSMEM>>>(
        pad, E, E, (const uint16_t*)xs_bf, (const uint16_t*)wattd_bf, b_attd);

    const dim3 gComb(NC/64, B/32, 4);   // 1024 blocks, KC=128 (4 k-tiles)
    const dim3 gAttd(E /64, B/32, 8);   // 256 blocks,  KC=256 (8 k-tiles)
    const dim3 gGate(G4/64, B/32, 4);   // 512 blocks,  KC=128 (4 k-tiles)
    const int  NLSTM = (B*H + 255)/256;

    // t = 0: gates_x = xs0 @ W_ih^T; comb slabs are zeroed by prep
    sgemm_pipe<32, 64, 32, 4, 0><<<gGate, 128>>>(
        slG, G4, xs, E, nullptr, 0, W_ih, E, B, G4, E, 128);
    k_lstm_red<<<NLSTM, 256>>>(slC, slG, bsum, hbuf, cbuf, hid_h);

    // t = 1..T
    for (int t = 1; t <= T; ++t) {
        // comb: [scores | gates_h] = h @ Wcomb^T  (splitK4 slabs)
        sgemm_pipe<32, 64, 32, 4, 0><<<gComb, 128>>>(
            slC, NC, hbuf, H, nullptr, 0, Wcomb, 512, B, NC, H, 128);

        // softmax(pan[t] + slabs) * cnn -> att
        k_softmax_att<<<B, 256>>>(pan + (size_t)t*B*A, slC, cnn, att);

        // attd: slD[z] = att @ W_attd[:, E:]^T slices (splitK8 slabs)
        sgemm_pipe<32, 64, 32, 4, 0><<<gAttd, 128>>>(
            slD, E, att, A, nullptr, 0, W_attd + E, E + A, B, E, A, 256);

        // gate_x: slG = (pad[t] + sum slD) @ W_ih^T  (A-loader fuses reduce)
        sgemm_pipe<32, 64, 32, 4, 8><<<gGate, 128>>>(
            slG, G4, pad + (size_t)t*B*E, E, slD, SLABD, W_ih, E, B, G4, E, 128);

        // LSTM pointwise (+ slab reductions + bias); h -> fp32 + fp16 row t
        k_lstm_red<<<NLSTM, 256>>>(slC, slG, bsum, hbuf, cbuf,
                                   hid_h + (size_t)t*B*KH1);
    }

    // logits = hidden @ W_out^T + b_out  (fp16 1-term, K=512)
    hmma_gemm<KH1, true><<<dim3(VPAD / 128, MALL / 128), 256, HSMEM>>>(
        out, V, V, (const uint16_t*)hid_h, (const uint16_t*)wout_h, b_out);
}

// round 9
// speedup vs baseline: 1.2348x; 1.0440x over previous
#include <cuda_runtime.h>
#include <cuda_bf16.h>
#include <cuda_fp16.h>
#include <math.h>
#include <stdint.h>
#include <utility>

// ---------------------------------------------------------------------------
// Problem constants
// ---------------------------------------------------------------------------
namespace {
constexpr int B   = 128;
constexpr int T   = 31;
constexpr int TP1 = 32;     // T+1
constexpr int E   = 512;
constexpr int H   = 512;
constexpr int V   = 10000;
constexpr int A   = 2048;
constexpr int G4  = 2048;   // 4*H
constexpr int NC  = 4096;   // comb GEMM cols: [scores | gates_h]
constexpr int MALL = TP1 * B;   // 4096
constexpr int VPAD = 10240;     // 80 * 128
constexpr int KBF  = 1536;      // 3 * 512 split-bf16 K (pan/pad)
constexpr int KH1  = 512;       // 1-term fp16 K (logits)

// scratch layout (floats) inside one __device__ buffer
constexpr size_t XS_OFF   = 0;                              // [TP1][B][E]
constexpr size_t PAN_OFF  = XS_OFF  + (size_t)TP1*B*E;      // [TP1][B][A]
constexpr size_t PAD_OFF  = PAN_OFF + (size_t)TP1*B*A;      // [TP1][B][E]
constexpr size_t H_OFF    = PAD_OFF + (size_t)TP1*B*E;      // [B][H]
constexpr size_t C_OFF    = H_OFF   + (size_t)B*H;          // [B][H]
constexpr size_t ATT_OFF  = C_OFF   + (size_t)B*H;          // [B][A]
constexpr size_t SLC_OFF  = ATT_OFF + (size_t)B*A;          // [4][B][NC]
constexpr size_t SLD_OFF  = SLC_OFF + (size_t)4*B*NC;       // [8][B][E]
constexpr size_t SLG_OFF  = SLD_OFF + (size_t)8*B*E;        // [4][B][G4]
constexpr size_t WC_OFF   = SLG_OFF + (size_t)4*B*G4;       // [NC][512] Wcomb
constexpr size_t BS_OFF   = WC_OFF  + (size_t)NC*512;       // [G4]
constexpr size_t BUF_TOTAL = BS_OFF + (size_t)G4;

constexpr int SLABD = B * E;     // slD slab stride (65536)
}

__device__ float g_buf[BUF_TOTAL];

// bf16 split operand buffers (pan/pad: 3-term)
__device__ __nv_bfloat16 g_xs_bf [(size_t)MALL * KBF];
__device__ __nv_bfloat16 g_wattn_bf[(size_t)A * KBF];
__device__ __nv_bfloat16 g_wattd_bf[(size_t)E * KBF];
// fp16 1-term buffers (logits)
__device__ __half g_hid_h [(size_t)MALL * KH1];
__device__ __half g_wout_h[(size_t)VPAD * KH1];

// PDL: wait for programmatic dependency (predecessor grid) before touching
// its outputs. Implicit trigger at predecessor completion => stream-order
// semantics, but grid launch latency is overlapped.
__device__ __forceinline__ void pdl_wait() {
    asm volatile("griddepcontrol.wait;" ::: "memory");
}

// ---------------------------------------------------------------------------
// Packed f32x2 FMA helpers
// ---------------------------------------------------------------------------
typedef unsigned long long ull;

__device__ __forceinline__ ull ffma2(ull a, ull b, ull c) {
    ull d;
    asm("fma.rn.f32x2 %0, %1, %2, %3;" : "=l"(d) : "l"(a), "l"(b), "l"(c));
    return d;
}
__device__ __forceinline__ ull dup2(float x) {
    ull d;
    asm("mov.b64 %0, {%1, %1};" : "=l"(d) : "f"(x));
    return d;
}
__device__ __forceinline__ float2 unpk(ull v) {
    float2 r;
    asm("mov.b64 {%0, %1}, %2;" : "=f"(r.x), "=f"(r.y) : "l"(v));
    return r;
}

// ---------------------------------------------------------------------------
// HMMA helpers (sm_80+ PTX)
// ---------------------------------------------------------------------------
__device__ __forceinline__ uint32_t smem_u32(const void* p) {
    uint32_t a;
    asm("{ .reg .u64 t; cvta.to.shared.u64 t, %1; cvt.u32.u64 %0, t; }"
        : "=r"(a) : "l"(p));
    return a;
}
__device__ __forceinline__ void cpa16(uint32_t s, const void* g) {
    asm volatile("cp.async.cg.shared.global [%0], [%1], 16;"
                 :: "r"(s), "l"(g));
}
#define CP_COMMIT() asm volatile("cp.async.commit_group;" ::: "memory")
#define CP_WAIT(N)  asm volatile("cp.async.wait_group %0;" :: "n"(N) : "memory")

#define LDSM4(R0, R1, R2, R3, ADDR) \
    asm volatile("ldmatrix.sync.aligned.m8n8.x4.shared.b16 {%0,%1,%2,%3}, [%4];" \
        : "=r"(R0), "=r"(R1), "=r"(R2), "=r"(R3) : "r"(ADDR))

template<bool FP16>
__device__ __forceinline__ void mma16816(float* d, const uint32_t* a,
                                         uint32_t b0, uint32_t b1) {
    if constexpr (FP16) {
        asm volatile(
            "mma.sync.aligned.m16n8k16.row.col.f32.f16.f16.f32 "
            "{%0,%1,%2,%3}, {%4,%5,%6,%7}, {%8,%9}, {%0,%1,%2,%3};"
            : "+f"(d[0]), "+f"(d[1]), "+f"(d[2]), "+f"(d[3])
            : "r"(a[0]), "r"(a[1]), "r"(a[2]), "r"(a[3]), "r"(b0), "r"(b1));
    } else {
        asm volatile(
            "mma.sync.aligned.m16n8k16.row.col.f32.bf16.bf16.f32 "
            "{%0,%1,%2,%3}, {%4,%5,%6,%7}, {%8,%9}, {%0,%1,%2,%3};"
            : "+f"(d[0]), "+f"(d[1]), "+f"(d[2]), "+f"(d[3])
            : "r"(a[0]), "r"(a[1]), "r"(a[2]), "r"(a[3]), "r"(b0), "r"(b1));
    }
}

namespace {
constexpr int HBK   = 32;
constexpr int HROWB = 80;            // 32 elems * 2B + 16B pad
constexpr int HSTG  = 256 * HROWB;   // 20480 B per stage
constexpr int HSMEM = 3 * HSTG;      // 61440 B
}

template<int KTOT, bool FP16>
__global__ void __launch_bounds__(256, 2)
hmma_gemm(float* __restrict__ C, int ldc, int Nreal,
          const uint16_t* __restrict__ Abf,
          const uint16_t* __restrict__ Bbf,
          const float* __restrict__ bias)
{
    pdl_wait();
    constexpr int NT = KTOT / HBK;
    extern __shared__ __align__(16) char sm[];
    const uint32_t sb = smem_u32(sm);

    const int tid  = threadIdx.x;
    const int wid  = tid >> 5;
    const int lane = tid & 31;
    const int wm   = wid & 1;
    const int wn   = wid >> 1;
    const int row0 = blockIdx.y * 128;
    const int col0 = blockIdx.x * 128;

    const int qr0 = (tid)       >> 2, qc0 = (tid)       & 3;
    const int qr1 = (tid + 256) >> 2, qc1 = (tid + 256) & 3;

    auto LOADG = [&](int t, int stg) {
        const int k0 = t * HBK;
        const uint32_t sa  = sb + stg * HSTG;
        const uint32_t sbm = sa + 128 * HROWB;
        cpa16(sa  + qr0 * HROWB + qc0 * 16,
              Abf + (size_t)(row0 + qr0) * KTOT + k0 + qc0 * 8);
        cpa16(sa  + qr1 * HROWB + qc1 * 16,
              Abf + (size_t)(row0 + qr1) * KTOT + k0 + qc1 * 8);
        cpa16(sbm + qr0 * HROWB + qc0 * 16,
              Bbf + (size_t)(col0 + qr0) * KTOT + k0 + qc0 * 8);
        cpa16(sbm + qr1 * HROWB + qc1 * 16,
              Bbf + (size_t)(col0 + qr1) * KTOT + k0 + qc1 * 8);
    };

    float acc[4][4][4];
#pragma unroll
    for (int i = 0; i < 4; ++i)
#pragma unroll
        for (int j = 0; j < 4; ++j)
#pragma unroll
            for (int q = 0; q < 4; ++q) acc[i][j][q] = 0.f;

    const int lr  = lane & 15;
    const int lkb = (lane >> 4) * 16;

    LOADG(0, 0); CP_COMMIT();
    LOADG(1, 1); CP_COMMIT();

    for (int t = 0; t < NT; ++t) {
        if (t + 1 < NT) { CP_WAIT(1); } else { CP_WAIT(0); }
        __syncthreads();
        if (t + 2 < NT) { LOADG(t + 2, (t + 2) % 3); CP_COMMIT(); }

        const uint32_t aB = sb + (t % 3) * HSTG;
        const uint32_t bB = aB + 128 * HROWB;
#pragma unroll
        for (int ks = 0; ks < 2; ++ks) {
            const int kbyte = ks * 32 + lkb;
            uint32_t af[4][4];
#pragma unroll
            for (int mf = 0; mf < 4; ++mf)
                LDSM4(af[mf][0], af[mf][1], af[mf][2], af[mf][3],
                      aB + (wm * 64 + mf * 16 + lr) * HROWB + kbyte);
            uint32_t bfr[2][4];
#pragma unroll
            for (int p = 0; p < 2; ++p)
                LDSM4(bfr[p][0], bfr[p][1], bfr[p][2], bfr[p][3],
                      bB + (wn * 32 + p * 16 + lr) * HROWB + kbyte);
#pragma unroll
            for (int mf = 0; mf < 4; ++mf)
#pragma unroll
                for (int nf = 0; nf < 4; ++nf)
                    mma16816<FP16>(acc[mf][nf], af[mf],
                                   bfr[nf >> 1][nf & 1], bfr[nf >> 1][(nf & 1) + 2]);
        }
    }

    const int rbase = row0 + wm * 64 + (lane >> 2);
    const int cbase = col0 + wn * 32 + 2 * (lane & 3);
#pragma unroll
    for (int nf = 0; nf < 4; ++nf) {
        const int col = cbase + nf * 8;
        if (col >= Nreal) continue;
        const float2 bv = *reinterpret_cast<const float2*>(bias + col);
#pragma unroll
        for (int mf = 0; mf < 4; ++mf) {
            const int r = rbase + mf * 16;
            *reinterpret_cast<float2*>(C + (size_t)r * ldc + col) =
                make_float2(acc[mf][nf][0] + bv.x, acc[mf][nf][1] + bv.y);
            *reinterpret_cast<float2*>(C + (size_t)(r + 8) * ldc + col) =
                make_float2(acc[mf][nf][2] + bv.x, acc[mf][nf][3] + bv.y);
        }
    }
}

// ---------------------------------------------------------------------------
// Conversion kernels
// ---------------------------------------------------------------------------
__global__ void k_split_a(const float* __restrict__ src,
                          __nv_bfloat16* __restrict__ dst, int M)
{
    pdl_wait();
    int i = blockIdx.x * blockDim.x + threadIdx.x;
    int n = M * 512;
    for (; i < n; i += gridDim.x * blockDim.x) {
        int m = i >> 9, j = i & 511;
        float x = src[i];
        __nv_bfloat16 hi = __float2bfloat16(x);
        __nv_bfloat16 lo = __float2bfloat16(x - __bfloat162float(hi));
        __nv_bfloat16* d = dst + (size_t)m * KBF;
        d[j] = hi; d[j + 512] = hi; d[j + 1024] = lo;
    }
}

__global__ void k_split_b(const float* __restrict__ src, int ld,
                          __nv_bfloat16* __restrict__ dst, int Nreal, int Npad)
{
    pdl_wait();
    int i = blockIdx.x * blockDim.x + threadIdx.x;
    int n = Npad * 512;
    for (; i < n; i += gridDim.x * blockDim.x) {
        int r = i >> 9, j = i & 511;
        float x = (r < Nreal) ? src[(size_t)r * ld + j] : 0.f;
        __nv_bfloat16 hi = __float2bfloat16(x);
        __nv_bfloat16 lo = __float2bfloat16(x - __bfloat162float(hi));
        __nv_bfloat16* d = dst + (size_t)r * KBF;
        d[j] = hi; d[j + 512] = lo; d[j + 1024] = hi;
    }
}

// fp16 1-term (W_out)
__global__ void k_split_b16(const float* __restrict__ src, int ld,
                            __half* __restrict__ dst, int Nreal, int Npad)
{
    pdl_wait();
    int i = blockIdx.x * blockDim.x + threadIdx.x;
    int n = Npad * 512;
    for (; i < n; i += gridDim.x * blockDim.x) {
        int r = i >> 9, j = i & 511;
        float x = (r < Nreal) ? src[(size_t)r * ld + j] : 0.f;
        dst[(size_t)r * KH1 + j] = __float2half(x);
    }
}

// ---------------------------------------------------------------------------
// Single-input pipelined fp32 SGEMM (recurrent path), split-K via gridDim.z.
// NSUM > 0: A tile = A[...] + sum of NSUM slabs (slab row length = lda).
// Proven FFMA2 core; BK=32; K, KC multiples of BK.
// ---------------------------------------------------------------------------
template<int BM, int BN, int BK, int TM, int NSUM>
__global__ void __launch_bounds__((BM/TM)*(BN/4))
sgemm_pipe(float* __restrict__ C, int ldc,
           const float* __restrict__ Ab, int lda,
           const float* __restrict__ slab, int slabstride,
           const float* __restrict__ W,  int ldw,
           int M, int N, int K, int KC)
{
    pdl_wait();
    constexpr int TN = 4;
    constexpr int THREADS = (BM/TM)*(BN/TN);
    constexpr int BMq = BM/4, BNq = BN/4, BKq = BK/4;
    constexpr int NA = (BM*BKq)/THREADS;
    constexpr int NW = (BN*BKq)/THREADS;

    __shared__ float4 As[2][BK][BMq];
    __shared__ float4 Ws[2][BK][BNq];

    const int tid  = threadIdx.x;
    const int tn   = tid % (BN/TN);
    const int tm   = tid / (BN/TN);
    const int row0 = blockIdx.y * BM;
    const int col0 = blockIdx.x * BN;
    const int kbeg = blockIdx.z * KC;
    const int kend = (kbeg + KC < K) ? (kbeg + KC) : K;
    const int ntile = (kend - kbeg) / BK;
    float* Cz = C + (size_t)blockIdx.z * M * N;

    ull acc[TM/2][TN];
#pragma unroll
    for (int i = 0; i < TM/2; ++i)
#pragma unroll
        for (int j = 0; j < TN; ++j) acc[i][j] = 0ULL;

    float4 ra[NA], rw[NW];

    auto LOADT = [&](int t) {
        const int k0 = kbeg + t * BK;
#pragma unroll
        for (int i = 0; i < NA; ++i) {
            int idx = tid + i * THREADS;
            int m = idx / BKq, kq = idx % BKq;
            int gm = row0 + m;
            float4 v = *reinterpret_cast<const float4*>(
                Ab + (size_t)gm*lda + k0 + kq*4);
            if (NSUM > 0) {
#pragma unroll
                for (int z = 0; z < NSUM; ++z) {
                    float4 s = *reinterpret_cast<const float4*>(
                        slab + (size_t)z*slabstride + (size_t)gm*lda + k0 + kq*4);
                    v.x += s.x; v.y += s.y; v.z += s.z; v.w += s.w;
                }
            }
            ra[i] = v;
        }
#pragma unroll
        for (int i = 0; i < NW; ++i) {
            int idx = tid + i * THREADS;
            int n = idx / BKq, kq = idx % BKq;
            int gn = col0 + n;
            rw[i] = *reinterpret_cast<const float4*>(
                W + (size_t)gn*ldw + k0 + kq*4);
        }
    };

    auto STORET = [&](int bsel) {
#pragma unroll
        for (int i = 0; i < NA; ++i) {
            int idx = tid + i * THREADS;
            int m = idx / BKq, kq = idx % BKq;
            const float* pv = reinterpret_cast<const float*>(&ra[i]);
#pragma unroll
            for (int r = 0; r < 4; ++r) {
                int k = kq*4 + r;
                int j = (m >> 2) ^ kq;
                reinterpret_cast<float*>(&As[bsel][k][j])[m & 3] = pv[r];
            }
        }
#pragma unroll
        for (int i = 0; i < NW; ++i) {
            int idx = tid + i * THREADS;
            int n = idx / BKq, kq = idx % BKq;
            const float* pv = reinterpret_cast<const float*>(&rw[i]);
#pragma unroll
            for (int r = 0; r < 4; ++r) {
                int k = kq*4 + r;
                int j = (n >> 2) ^ kq;
                reinterpret_cast<float*>(&Ws[bsel][k][j])[n & 3] = pv[r];
            }
        }
    };

    auto COMP = [&](int bsel) {
#pragma unroll
        for (int k = 0; k < BK; ++k) {
            const int s = (k >> 2) & 7;
            ull a2[TM/2];
#pragma unroll
            for (int q = 0; q < TM/4; ++q) {
                ulonglong2 p = *reinterpret_cast<const ulonglong2*>(
                    &As[bsel][k][(tm*(TM/4) + q) ^ s]);
                a2[2*q]   = p.x;
                a2[2*q+1] = p.y;
            }
            float4 wv = Ws[bsel][k][tn ^ s];
            ull w0 = dup2(wv.x), w1 = dup2(wv.y), w2 = dup2(wv.z), w3 = dup2(wv.w);
#pragma unroll
            for (int i = 0; i < TM/2; ++i) {
                acc[i][0] = ffma2(a2[i], w0, acc[i][0]);
                acc[i][1] = ffma2(a2[i], w1, acc[i][1]);
                acc[i][2] = ffma2(a2[i], w2, acc[i][2]);
                acc[i][3] = ffma2(a2[i], w3, acc[i][3]);
            }
        }
    };

    if (ntile > 0) {
        LOADT(0);
        STORET(0);
        __syncthreads();
        for (int t = 0; t < ntile; ++t) {
            if (t + 1 < ntile) LOADT(t + 1);
            COMP(t & 1);
            if (t + 1 < ntile) {
                __syncthreads();
                STORET((t + 1) & 1);
                __syncthreads();
            }
        }
    }

    const int cc = col0 + tn*TN;
#pragma unroll
    for (int i = 0; i < TM/2; ++i) {
        float2 u[TN];
#pragma unroll
        for (int j = 0; j < TN; ++j) u[j] = unpk(acc[i][j]);
#pragma unroll
        for (int rr = 0; rr < 2; ++rr) {
            int r = row0 + tm*TM + 2*i + rr;
            float* cp = Cz + (size_t)r*ldc + cc;
            *reinterpret_cast<float4*>(cp) = make_float4(
                rr == 0 ? u[0].x : u[0].y, rr == 0 ? u[1].x : u[1].y,
                rr == 0 ? u[2].x : u[2].y, rr == 0 ? u[3].x : u[3].y);
        }
    }
}

// ---------------------------------------------------------------------------
// Prep kernels
// ---------------------------------------------------------------------------
__global__ void k_prep(const float* __restrict__ b_ih, const float* __restrict__ b_hh,
                       const float* __restrict__ W_attn, const float* __restrict__ W_hh)
{
    int idx = blockIdx.x * blockDim.x + threadIdx.x;
    int stride = gridDim.x * blockDim.x;
    for (int i = idx; i < B*H; i += stride) {
        g_buf[H_OFF + i] = 0.f;
        g_buf[C_OFF + i] = 0.f;
    }
    for (int i = idx; i < 4*B*NC; i += stride)
        g_buf[SLC_OFF + i] = 0.f;
    for (int i = idx; i < G4; i += stride)
        g_buf[BS_OFF + i] = b_ih[i] + b_hh[i];
    // Wcomb[4096][512]: rows 0..2047 = W_attn[:, E:], rows 2048.. = W_hh
    for (int i = idx; i < NC*512; i += stride) {
        int r = i >> 9, k = i & 511;
        g_buf[WC_OFF + i] = (r < A) ? W_attn[(size_t)r*(E+H) + E + k]
                                    : W_hh[(size_t)(r - A)*H + k];
    }
}

__global__ void k_build_xs(const float* __restrict__ features,
                           const int*   __restrict__ captions,
                           const float* __restrict__ embed)
{
    pdl_wait();
    int idx = blockIdx.x * blockDim.x + threadIdx.x;
    int stride = gridDim.x * blockDim.x;
    for (int i = idx; i < TP1*B*E; i += stride) {
        int e  = i & (E - 1);
        int be = i >> 9;
        int b  = be & (B - 1);
        int t  = be >> 7;
        float v;
        if (t == 0) {
            v = features[b*E + e];
        } else {
            int tok = captions[b*T + (t - 1)];
            v = embed[(size_t)tok*E + e];
        }
        g_buf[XS_OFF + i] = v;
    }
}

// ---------------------------------------------------------------------------
// softmax(pan[t] + 4 comb slabs cols[0:A]) * cnn -> att
// ---------------------------------------------------------------------------
__global__ void __launch_bounds__(256)
k_softmax_att(const float* __restrict__ pre,
              const float* __restrict__ slc,
              const float* __restrict__ cnn,
              float* __restrict__ att)
{
    pdl_wait();
    int b = blockIdx.x;
    int t = threadIdx.x;
    const size_t o0 = (size_t)b*A;
    const float* s0 = slc + (size_t)b*NC;
    const size_t SS = (size_t)B*NC;
    float v[8];
    float mx = -1e30f;
#pragma unroll
    for (int i = 0; i < 8; ++i) {
        int j = t + 256*i;
        float s = pre[o0 + j] + s0[j] + s0[j + SS] + s0[j + 2*SS] + s0[j + 3*SS];
        v[i] = s;
        mx = fmaxf(mx, s);
    }
    __shared__ float red[256];
    red[t] = mx; __syncthreads();
    for (int off = 128; off > 0; off >>= 1) {
        if (t < off) red[t] = fmaxf(red[t], red[t + off]);
        __syncthreads();
    }
    mx = red[0]; __syncthreads();

    float sum = 0.f;
#pragma unroll
    for (int i = 0; i < 8; ++i) {
        v[i] = expf(v[i] - mx);
        sum += v[i];
    }
    red[t] = sum; __syncthreads();
    for (int off = 128; off > 0; off >>= 1) {
        if (t < off) red[t] += red[t + off];
        __syncthreads();
    }
    float inv = 1.f / red[0];

    const float* cb = cnn + o0;
    float* ab = att + o0;
#pragma unroll
    for (int i = 0; i < 8; ++i)
        ab[t + 256*i] = cb[t + 256*i] * v[i] * inv;
}

// LSTM pointwise: gates = bsum + 4 comb slabs (cols A..) + 4 gate_x slabs.
// h written fp32 (next-step GEMM input) and fp16 (logits operand).
__global__ void __launch_bounds__(256)
k_lstm_red(const float* __restrict__ slc,
           const float* __restrict__ slg,
           const float* __restrict__ bsum,
           float* __restrict__ h, float* __restrict__ c,
           __half* __restrict__ hid16)
{
    pdl_wait();
    int idx = blockIdx.x * blockDim.x + threadIdx.x;
    if (idx >= B*H) return;
    int b = idx >> 9;
    int j = idx & 511;
    float gi = bsum[j], gf = bsum[j + 512], gg = bsum[j + 1024], go = bsum[j + 1536];
#pragma unroll
    for (int z = 0; z < 4; ++z) {
        const float* gc = slc + (size_t)z*B*NC + (size_t)b*NC + A;
        const float* gx = slg + (size_t)z*B*G4 + (size_t)b*G4;
        gi += gc[j]        + gx[j];
        gf += gc[j + 512]  + gx[j + 512];
        gg += gc[j + 1024] + gx[j + 1024];
        go += gc[j + 1536] + gx[j + 1536];
    }
    float ig = 1.f / (1.f + expf(-gi));
    float fg = 1.f / (1.f + expf(-gf));
    float gt = tanhf(gg);
    float og = 1.f / (1.f + expf(-go));
    float cn = fg * c[idx] + ig * gt;
    float hn = og * tanhf(cn);
    c[idx] = cn;
    h[idx] = hn;
    hid16[(size_t)b * KH1 + j] = __float2half(hn);
}

// ---------------------------------------------------------------------------
// Host: PDL launch helper (programmatic stream serialization on every node)
// ---------------------------------------------------------------------------
template<typename F, typename... Args>
static inline void pdl_launch(F func, dim3 gd, dim3 bd, size_t sh, Args... args)
{
    cudaLaunchConfig_t cfg = {};
    cfg.gridDim = gd;
    cfg.blockDim = bd;
    cfg.dynamicSmemBytes = sh;
    cudaLaunchAttribute attr[1];
    attr[0].id = cudaLaunchAttributeProgrammaticStreamSerialization;
    attr[0].val.programmaticStreamSerializationAllowed = 1;
    cfg.attrs = attr;
    cfg.numAttrs = 1;
    cudaLaunchKernelEx(&cfg, func, args...);
}

// ---------------------------------------------------------------------------
// Host launch sequence (graph-capturable: kernel launches only)
// ---------------------------------------------------------------------------
extern "C" void kernel_launch(void* const* d_in, const int* in_sizes, int n_in,
                              void* d_out, int out_size)
{
    const float* features = (const float*)d_in[0];
    const float* cnn      = (const float*)d_in[1];
    const int*   captions = (const int*)  d_in[2];
    /* d_in[3] = lengths (unused: all T+1) */
    const float* embed    = (const float*)d_in[4];
    const float* W_ih     = (const float*)d_in[5];
    const float* W_hh     = (const float*)d_in[6];
    const float* b_ih     = (const float*)d_in[7];
    const float* b_hh     = (const float*)d_in[8];
    const float* W_attn   = (const float*)d_in[9];
    const float* b_attn   = (const float*)d_in[10];
    const float* W_attd   = (const float*)d_in[11];
    const float* b_attd   = (const float*)d_in[12];
    const float* W_out    = (const float*)d_in[13];
    const float* b_out    = (const float*)d_in[14];
    float* out = (float*)d_out;

    float* buf = nullptr;
    cudaGetSymbolAddress((void**)&buf, g_buf);
    __nv_bfloat16 *xs_bf, *wattn_bf, *wattd_bf;
    __half *hid_h, *wout_h;
    cudaGetSymbolAddress((void**)&xs_bf,    g_xs_bf);
    cudaGetSymbolAddress((void**)&wattn_bf, g_wattn_bf);
    cudaGetSymbolAddress((void**)&wattd_bf, g_wattd_bf);
    cudaGetSymbolAddress((void**)&hid_h,    g_hid_h);
    cudaGetSymbolAddress((void**)&wout_h,   g_wout_h);

    cudaFuncSetAttribute(hmma_gemm<KBF, false>,
                         cudaFuncAttributeMaxDynamicSharedMemorySize, HSMEM);
    cudaFuncSetAttribute(hmma_gemm<KH1, true>,
                         cudaFuncAttributeMaxDynamicSharedMemorySize, HSMEM);

    float* xs    = buf + XS_OFF;
    float* pan   = buf + PAN_OFF;
    float* pad   = buf + PAD_OFF;
    float* hbuf  = buf + H_OFF;
    float* cbuf  = buf + C_OFF;
    float* att   = buf + ATT_OFF;
    float* slC   = buf + SLC_OFF;
    float* slD   = buf + SLD_OFF;
    float* slG   = buf + SLG_OFF;
    float* Wcomb = buf + WC_OFF;
    float* bsum  = buf + BS_OFF;

    // prep
    pdl_launch(k_prep, dim3(2048), dim3(256), 0, b_ih, b_hh, W_attn, W_hh);
    pdl_launch(k_build_xs, dim3(2048), dim3(256), 0, features, captions, embed);

    // conversions
    pdl_launch(k_split_a, dim3(4096), dim3(256), 0,
               (const float*)xs, xs_bf, (int)MALL);
    pdl_launch(k_split_b, dim3(2048), dim3(256), 0,
               W_attn, (int)(E + H), wattn_bf, (int)A, (int)A);
    pdl_launch(k_split_b, dim3(1024), dim3(256), 0,
               W_attd, (int)(E + A), wattd_bf, (int)E, (int)E);
    pdl_launch(k_split_b16, dim3(4096), dim3(256), 0,
               W_out, (int)H, wout_h, (int)V, (int)VPAD);

    // pan[t] = x_t @ W_attn[:, :E]^T + b_attn  (bf16 3-term)
    pdl_launch(hmma_gemm<KBF, false>, dim3(A / 128, MALL / 128), dim3(256), (size_t)HSMEM,
               pan, (int)A, (int)A,
               (const uint16_t*)xs_bf, (const uint16_t*)wattn_bf, b_attn);
    // pad[t] = x_t @ W_attd[:, :E]^T + b_attd  (bf16 3-term)
    pdl_launch(hmma_gemm<KBF, false>, dim3(E / 128, MALL / 128), dim3(256), (size_t)HSMEM,
               pad, (int)E, (int)E,
               (const uint16_t*)xs_bf, (const uint16_t*)wattd_bf, b_attd);

    const dim3 gComb(NC/64, B/32, 4);   // 1024 blocks, KC=128 (4 k-tiles)
    const dim3 gAttd(E /64, B/32, 8);   // 256 blocks,  KC=256 (8 k-tiles)
    const dim3 gGate(G4/64, B/32, 4);   // 512 blocks,  KC=128 (4 k-tiles)
    const int  NLSTM = (B*H + 255)/256;

    // t = 0: gates_x = xs0 @ W_ih^T; comb slabs are zeroed by prep
    pdl_launch(sgemm_pipe<32, 64, 32, 4, 0>, gGate, dim3(128), 0,
               slG, (int)G4, (const float*)xs, (int)E,
               (const float*)nullptr, 0, W_ih, (int)E,
               (int)B, (int)G4, (int)E, 128);
    pdl_launch(k_lstm_red, dim3(NLSTM), dim3(256), 0,
               (const float*)slC, (const float*)slG, (const float*)bsum,
               hbuf, cbuf, hid_h);

    // t = 1..T
    for (int t = 1; t <= T; ++t) {
        // comb: [scores | gates_h] = h @ Wcomb^T  (splitK4 slabs)
        pdl_launch(sgemm_pipe<32, 64, 32, 4, 0>, gComb, dim3(128), 0,
                   slC, (int)NC, (const float*)hbuf, (int)H,
                   (const float*)nullptr, 0, (const float*)Wcomb, 512,
                   (int)B, (int)NC, (int)H, 128);

        // softmax(pan[t] + slabs) * cnn -> att
        pdl_launch(k_softmax_att, dim3(B), dim3(256), 0,
                   (const float*)(pan + (size_t)t*B*A), (const float*)slC,
                   cnn, att);

        // attd: slD[z] = att @ W_attd[:, E:]^T slices (splitK8 slabs)
        pdl_launch(sgemm_pipe<32, 64, 32, 4, 0>, gAttd, dim3(128), 0,
                   slD, (int)E, (const float*)att, (int)A,
                   (const float*)nullptr, 0, W_attd + E, (int)(E + A),
                   (int)B, (int)E, (int)A, 256);

        // gate_x: slG = (pad[t] + sum slD) @ W_ih^T  (A-loader fuses reduce)
        pdl_launch(sgemm_pipe<32, 64, 32, 4, 8>, gGate, dim3(128), 0,
                   slG, (int)G4, (const float*)(pad + (size_t)t*B*E), (int)E,
                   (const float*)slD, (int)SLABD, W_ih, (int)E,
                   (int)B, (int)G4, (int)E, 128);

        // LSTM pointwise (+ slab reductions + bias); h -> fp32 + fp16 row t
        pdl_launch(k_lstm_red, dim3(NLSTM), dim3(256), 0,
                   (const float*)slC, (const float*)slG, (const float*)bsum,
                   hbuf, cbuf, hid_h + (size_t)t*B*KH1);
    }

    // logits = hidden @ W_out^T + b_out  (fp16 1-term, K=512)
    pdl_launch(hmma_gemm<KH1, true>, dim3(VPAD / 128, MALL / 128), dim3(256),
               (size_t)HSMEM,
               out, (int)V, (int)V,
               (const uint16_t*)hid_h, (const uint16_t*)wout_h, b_out);
}

// round 10
// speedup vs baseline: 1.6161x; 1.3087x over previous
#include <cuda_runtime.h>
#include <cuda_bf16.h>
#include <cuda_fp16.h>
#include <math.h>
#include <stdint.h>
#include <utility>

// ---------------------------------------------------------------------------
// Problem constants
// ---------------------------------------------------------------------------
namespace {
constexpr int B   = 128;
constexpr int T   = 31;
constexpr int TP1 = 32;     // T+1
constexpr int E   = 512;
constexpr int H   = 512;
constexpr int V   = 10000;
constexpr int A   = 2048;
constexpr int G4  = 2048;   // 4*H
constexpr int NC  = 4096;   // comb cols: [scores | gates_h]
constexpr int MALL = TP1 * B;   // 4096
constexpr int VPAD = 10240;     // 80 * 128
constexpr int KBF  = 1536;      // 3 * 512 split-bf16 K
constexpr int KBFA = 6144;      // 3 * 2048 split-bf16 K (attd)
constexpr int KH1  = 512;       // 1-term fp16 K (logits)

// fp32 scratch layout
constexpr size_t XS_OFF   = 0;                              // [TP1][B][E]
constexpr size_t PAN_OFF  = XS_OFF  + (size_t)TP1*B*E;      // [TP1][B][A]
constexpr size_t PAD_OFF  = PAN_OFF + (size_t)TP1*B*A;      // [TP1][B][E]
constexpr size_t C_OFF    = PAD_OFF + (size_t)TP1*B*E;      // [B][H]
constexpr size_t SLC_OFF  = C_OFF   + (size_t)B*H;          // [4][B][NC]
constexpr size_t SLD_OFF  = SLC_OFF + (size_t)4*B*NC;       // [32][B][E]
constexpr size_t SLG_OFF  = SLD_OFF + (size_t)32*B*E;       // [8][B][G4]
constexpr size_t BS_OFF   = SLG_OFF + (size_t)8*B*G4;       // [G4]
constexpr size_t BUF_TOTAL = BS_OFF + (size_t)G4;
}

__device__ float g_buf[BUF_TOTAL];

// bf16 split operand buffers
__device__ __nv_bfloat16 g_xs_bf   [(size_t)MALL * KBF];   // A-side [hi|hi|lo]
__device__ __nv_bfloat16 g_wattn_bf[(size_t)A * KBF];      // B-side (pan)
__device__ __nv_bfloat16 g_wattd_bf[(size_t)E * KBF];      // B-side (pad)
__device__ __nv_bfloat16 g_h_bf    [(size_t)B * KBF];      // A-side h
__device__ __nv_bfloat16 g_att_bf  [(size_t)B * KBFA];     // A-side att
__device__ __nv_bfloat16 g_x2_bf   [(size_t)B * KBF];      // A-side x2
__device__ __nv_bfloat16 g_wcomb_bf[(size_t)NC * KBF];     // B-side comb W
__device__ __nv_bfloat16 g_wih_bf  [(size_t)G4 * KBF];     // B-side W_ih
__device__ __nv_bfloat16 g_wattd2_bf[(size_t)E * KBFA];    // B-side W_attd[:,E:]
// fp16 1-term buffers (logits)
__device__ __half g_hid_h [(size_t)MALL * KH1];
__device__ __half g_wout_h[(size_t)VPAD * KH1];

__device__ __forceinline__ void pdl_wait() {
    asm volatile("griddepcontrol.wait;" ::: "memory");
}

// split helpers
__device__ __forceinline__ void split_bf(float x, __nv_bfloat16& hi, __nv_bfloat16& lo) {
    hi = __float2bfloat16(x);
    lo = __float2bfloat16(x - __bfloat162float(hi));
}

// ---------------------------------------------------------------------------
// HMMA helpers (sm_80+ PTX)
// ---------------------------------------------------------------------------
__device__ __forceinline__ uint32_t smem_u32(const void* p) {
    uint32_t a;
    asm("{ .reg .u64 t; cvta.to.shared.u64 t, %1; cvt.u32.u64 %0, t; }"
        : "=r"(a) : "l"(p));
    return a;
}
__device__ __forceinline__ void cpa16(uint32_t s, const void* g) {
    asm volatile("cp.async.cg.shared.global [%0], [%1], 16;"
                 :: "r"(s), "l"(g));
}
#define CP_COMMIT() asm volatile("cp.async.commit_group;" ::: "memory")
#define CP_WAIT(N)  asm volatile("cp.async.wait_group %0;" :: "n"(N) : "memory")

#define LDSM4(R0, R1, R2, R3, ADDR) \
    asm volatile("ldmatrix.sync.aligned.m8n8.x4.shared.b16 {%0,%1,%2,%3}, [%4];" \
        : "=r"(R0), "=r"(R1), "=r"(R2), "=r"(R3) : "r"(ADDR))

template<bool FP16>
__device__ __forceinline__ void mma16816(float* d, const uint32_t* a,
                                         uint32_t b0, uint32_t b1) {
    if constexpr (FP16) {
        asm volatile(
            "mma.sync.aligned.m16n8k16.row.col.f32.f16.f16.f32 "
            "{%0,%1,%2,%3}, {%4,%5,%6,%7}, {%8,%9}, {%0,%1,%2,%3};"
            : "+f"(d[0]), "+f"(d[1]), "+f"(d[2]), "+f"(d[3])
            : "r"(a[0]), "r"(a[1]), "r"(a[2]), "r"(a[3]), "r"(b0), "r"(b1));
    } else {
        asm volatile(
            "mma.sync.aligned.m16n8k16.row.col.f32.bf16.bf16.f32 "
            "{%0,%1,%2,%3}, {%4,%5,%6,%7}, {%8,%9}, {%0,%1,%2,%3};"
            : "+f"(d[0]), "+f"(d[1]), "+f"(d[2]), "+f"(d[3])
            : "r"(a[0]), "r"(a[1]), "r"(a[2]), "r"(a[3]), "r"(b0), "r"(b1));
    }
}

namespace {
constexpr int HBK   = 32;
constexpr int HROWB = 80;            // 32 elems * 2B + 16B pad
constexpr int HSTG  = 256 * HROWB;   // 20480 B per stage
constexpr int HSMEM = 3 * HSTG;      // 61440 B
}

// ---------------------------------------------------------------------------
// hmma_gemm: big parallel GEMMs (pan/pad/logits). Compile-time K.
// ---------------------------------------------------------------------------
template<int KTOT, bool FP16>
__global__ void __launch_bounds__(256, 2)
hmma_gemm(float* __restrict__ C, int ldc, int Nreal,
          const uint16_t* __restrict__ Abf,
          const uint16_t* __restrict__ Bbf,
          const float* __restrict__ bias)
{
    pdl_wait();
    constexpr int NT = KTOT / HBK;
    extern __shared__ __align__(16) char sm[];
    const uint32_t sb = smem_u32(sm);

    const int tid  = threadIdx.x;
    const int wid  = tid >> 5;
    const int lane = tid & 31;
    const int wm   = wid & 1;
    const int wn   = wid >> 1;
    const int row0 = blockIdx.y * 128;
    const int col0 = blockIdx.x * 128;

    const int qr0 = (tid)       >> 2, qc0 = (tid)       & 3;
    const int qr1 = (tid + 256) >> 2, qc1 = (tid + 256) & 3;

    auto LOADG = [&](int t, int stg) {
        const int k0 = t * HBK;
        const uint32_t sa  = sb + stg * HSTG;
        const uint32_t sbm = sa + 128 * HROWB;
        cpa16(sa  + qr0 * HROWB + qc0 * 16,
              Abf + (size_t)(row0 + qr0) * KTOT + k0 + qc0 * 8);
        cpa16(sa  + qr1 * HROWB + qc1 * 16,
              Abf + (size_t)(row0 + qr1) * KTOT + k0 + qc1 * 8);
        cpa16(sbm + qr0 * HROWB + qc0 * 16,
              Bbf + (size_t)(col0 + qr0) * KTOT + k0 + qc0 * 8);
        cpa16(sbm + qr1 * HROWB + qc1 * 16,
              Bbf + (size_t)(col0 + qr1) * KTOT + k0 + qc1 * 8);
    };

    float acc[4][4][4];
#pragma unroll
    for (int i = 0; i < 4; ++i)
#pragma unroll
        for (int j = 0; j < 4; ++j)
#pragma unroll
            for (int q = 0; q < 4; ++q) acc[i][j][q] = 0.f;

    const int lr  = lane & 15;
    const int lkb = (lane >> 4) * 16;

    LOADG(0, 0); CP_COMMIT();
    LOADG(1, 1); CP_COMMIT();

    for (int t = 0; t < NT; ++t) {
        if (t + 1 < NT) { CP_WAIT(1); } else { CP_WAIT(0); }
        __syncthreads();
        if (t + 2 < NT) { LOADG(t + 2, (t + 2) % 3); CP_COMMIT(); }

        const uint32_t aB = sb + (t % 3) * HSTG;
        const uint32_t bB = aB + 128 * HROWB;
#pragma unroll
        for (int ks = 0; ks < 2; ++ks) {
            const int kbyte = ks * 32 + lkb;
            uint32_t af[4][4];
#pragma unroll
            for (int mf = 0; mf < 4; ++mf)
                LDSM4(af[mf][0], af[mf][1], af[mf][2], af[mf][3],
                      aB + (wm * 64 + mf * 16 + lr) * HROWB + kbyte);
            uint32_t bfr[2][4];
#pragma unroll
            for (int p = 0; p < 2; ++p)
                LDSM4(bfr[p][0], bfr[p][1], bfr[p][2], bfr[p][3],
                      bB + (wn * 32 + p * 16 + lr) * HROWB + kbyte);
#pragma unroll
            for (int mf = 0; mf < 4; ++mf)
#pragma unroll
                for (int nf = 0; nf < 4; ++nf)
                    mma16816<FP16>(acc[mf][nf], af[mf],
                                   bfr[nf >> 1][nf & 1], bfr[nf >> 1][(nf & 1) + 2]);
        }
    }

    const int rbase = row0 + wm * 64 + (lane >> 2);
    const int cbase = col0 + wn * 32 + 2 * (lane & 3);
#pragma unroll
    for (int nf = 0; nf < 4; ++nf) {
        const int col = cbase + nf * 8;
        if (col >= Nreal) continue;
        const float2 bv = *reinterpret_cast<const float2*>(bias + col);
#pragma unroll
        for (int mf = 0; mf < 4; ++mf) {
            const int r = rbase + mf * 16;
            *reinterpret_cast<float2*>(C + (size_t)r * ldc + col) =
                make_float2(acc[mf][nf][0] + bv.x, acc[mf][nf][1] + bv.y);
            *reinterpret_cast<float2*>(C + (size_t)(r + 8) * ldc + col) =
                make_float2(acc[mf][nf][2] + bv.x, acc[mf][nf][3] + bv.y);
        }
    }
}

// ---------------------------------------------------------------------------
// hmma_rec: recurrent-step GEMM. M = 128 (one row block), runtime K range,
// split-K slab output (z-slab = blockIdx.z), no bias, N multiple of 128.
// lda applies to BOTH operands (layouts arranged so lda == ldb).
// ---------------------------------------------------------------------------
__global__ void __launch_bounds__(256, 2)
hmma_rec(float* __restrict__ C, int N,
         const uint16_t* __restrict__ Abf,
         const uint16_t* __restrict__ Bbf, int lda,
         int KC)
{
    pdl_wait();
    extern __shared__ __align__(16) char sm[];
    const uint32_t sb = smem_u32(sm);

    const int NT   = KC / HBK;
    const int kbeg = blockIdx.z * KC;
    const int tid  = threadIdx.x;
    const int wid  = tid >> 5;
    const int lane = tid & 31;
    const int wm   = wid & 1;
    const int wn   = wid >> 1;
    const int col0 = blockIdx.x * 128;
    float* Cz = C + (size_t)blockIdx.z * 128 * N;

    const int qr0 = (tid)       >> 2, qc0 = (tid)       & 3;
    const int qr1 = (tid + 256) >> 2, qc1 = (tid + 256) & 3;

    auto LOADG = [&](int t, int stg) {
        const int k0 = kbeg + t * HBK;
        const uint32_t sa  = sb + stg * HSTG;
        const uint32_t sbm = sa + 128 * HROWB;
        cpa16(sa  + qr0 * HROWB + qc0 * 16,
              Abf + (size_t)qr0 * lda + k0 + qc0 * 8);
        cpa16(sa  + qr1 * HROWB + qc1 * 16,
              Abf + (size_t)qr1 * lda + k0 + qc1 * 8);
        cpa16(sbm + qr0 * HROWB + qc0 * 16,
              Bbf + (size_t)(col0 + qr0) * lda + k0 + qc0 * 8);
        cpa16(sbm + qr1 * HROWB + qc1 * 16,
              Bbf + (size_t)(col0 + qr1) * lda + k0 + qc1 * 8);
    };

    float acc[4][4][4];
#pragma unroll
    for (int i = 0; i < 4; ++i)
#pragma unroll
        for (int j = 0; j < 4; ++j)
#pragma unroll
            for (int q = 0; q < 4; ++q) acc[i][j][q] = 0.f;

    const int lr  = lane & 15;
    const int lkb = (lane >> 4) * 16;

    LOADG(0, 0); CP_COMMIT();
    LOADG(1, 1); CP_COMMIT();

    for (int t = 0; t < NT; ++t) {
        if (t + 1 < NT) { CP_WAIT(1); } else { CP_WAIT(0); }
        __syncthreads();
        if (t + 2 < NT) { LOADG(t + 2, (t + 2) % 3); CP_COMMIT(); }

        const uint32_t aB = sb + (t % 3) * HSTG;
        const uint32_t bB = aB + 128 * HROWB;
#pragma unroll
        for (int ks = 0; ks < 2; ++ks) {
            const int kbyte = ks * 32 + lkb;
            uint32_t af[4][4];
#pragma unroll
            for (int mf = 0; mf < 4; ++mf)
                LDSM4(af[mf][0], af[mf][1], af[mf][2], af[mf][3],
                      aB + (wm * 64 + mf * 16 + lr) * HROWB + kbyte);
            uint32_t bfr[2][4];
#pragma unroll
            for (int p = 0; p < 2; ++p)
                LDSM4(bfr[p][0], bfr[p][1], bfr[p][2], bfr[p][3],
                      bB + (wn * 32 + p * 16 + lr) * HROWB + kbyte);
#pragma unroll
            for (int mf = 0; mf < 4; ++mf)
#pragma unroll
                for (int nf = 0; nf < 4; ++nf)
                    mma16816<false>(acc[mf][nf], af[mf],
                                    bfr[nf >> 1][nf & 1], bfr[nf >> 1][(nf & 1) + 2]);
        }
    }

    const int rbase = wm * 64 + (lane >> 2);
    const int cbase = col0 + wn * 32 + 2 * (lane & 3);
#pragma unroll
    for (int nf = 0; nf < 4; ++nf) {
        const int col = cbase + nf * 8;
#pragma unroll
        for (int mf = 0; mf < 4; ++mf) {
            const int r = rbase + mf * 16;
            *reinterpret_cast<float2*>(Cz + (size_t)r * N + col) =
                make_float2(acc[mf][nf][0], acc[mf][nf][1]);
            *reinterpret_cast<float2*>(Cz + (size_t)(r + 8) * N + col) =
                make_float2(acc[mf][nf][2], acc[mf][nf][3]);
        }
    }
}

// ---------------------------------------------------------------------------
// Conversion kernels
// ---------------------------------------------------------------------------
// A-side 3-term: [hi | hi | lo], Korig=512
__global__ void k_split_a(const float* __restrict__ src,
                          __nv_bfloat16* __restrict__ dst, int M)
{
    pdl_wait();
    int i = blockIdx.x * blockDim.x + threadIdx.x;
    int n = M * 512;
    for (; i < n; i += gridDim.x * blockDim.x) {
        int m = i >> 9, j = i & 511;
        __nv_bfloat16 hi, lo;
        split_bf(src[i], hi, lo);
        __nv_bfloat16* d = dst + (size_t)m * KBF;
        d[j] = hi; d[j + 512] = hi; d[j + 1024] = lo;
    }
}

// B-side 3-term: [hi | lo | hi], Korig=512
__global__ void k_split_b(const float* __restrict__ src, int ld,
                          __nv_bfloat16* __restrict__ dst, int Nreal, int Npad)
{
    pdl_wait();
    int i = blockIdx.x * blockDim.x + threadIdx.x;
    int n = Npad * 512;
    for (; i < n; i += gridDim.x * blockDim.x) {
        int r = i >> 9, j = i & 511;
        float x = (r < Nreal) ? src[(size_t)r * ld + j] : 0.f;
        __nv_bfloat16 hi, lo;
        split_bf(x, hi, lo);
        __nv_bfloat16* d = dst + (size_t)r * KBF;
        d[j] = hi; d[j + 512] = lo; d[j + 1024] = hi;
    }
}

// fp16 1-term (W_out)
__global__ void k_split_b16(const float* __restrict__ src, int ld,
                            __half* __restrict__ dst, int Nreal, int Npad)
{
    pdl_wait();
    int i = blockIdx.x * blockDim.x + threadIdx.x;
    int n = Npad * 512;
    for (; i < n; i += gridDim.x * blockDim.x) {
        int r = i >> 9, j = i & 511;
        float x = (r < Nreal) ? src[(size_t)r * ld + j] : 0.f;
        dst[(size_t)r * KH1 + j] = __float2half(x);
    }
}

// ---------------------------------------------------------------------------
// Prep: zero c/slC, fuse biases, build B-side split weights for recurrence
// ---------------------------------------------------------------------------
__global__ void k_prep(const float* __restrict__ b_ih, const float* __restrict__ b_hh,
                       const float* __restrict__ W_attn, const float* __restrict__ W_hh,
                       const float* __restrict__ W_ih, const float* __restrict__ W_attd)
{
    int idx = blockIdx.x * blockDim.x + threadIdx.x;
    int stride = gridDim.x * blockDim.x;
    for (int i = idx; i < B*H; i += stride)
        g_buf[C_OFF + i] = 0.f;
    for (int i = idx; i < 4*B*NC; i += stride)
        g_buf[SLC_OFF + i] = 0.f;
    for (int i = idx; i < G4; i += stride)
        g_buf[BS_OFF + i] = b_ih[i] + b_hh[i];
    // Wcomb_bf [4096][1536]: rows 0..2047 = W_attn[:, E:], rows 2048.. = W_hh
    for (int i = idx; i < NC*512; i += stride) {
        int r = i >> 9, k = i & 511;
        float x = (r < A) ? W_attn[(size_t)r*(E+H) + E + k]
                          : W_hh[(size_t)(r - A)*H + k];
        __nv_bfloat16 hi, lo;
        split_bf(x, hi, lo);
        __nv_bfloat16* d = g_wcomb_bf + (size_t)r * KBF;
        d[k] = hi; d[k + 512] = lo; d[k + 1024] = hi;
    }
    // Wih_bf [2048][1536]
    for (int i = idx; i < G4*512; i += stride) {
        int r = i >> 9, k = i & 511;
        __nv_bfloat16 hi, lo;
        split_bf(W_ih[(size_t)r*E + k], hi, lo);
        __nv_bfloat16* d = g_wih_bf + (size_t)r * KBF;
        d[k] = hi; d[k + 512] = lo; d[k + 1024] = hi;
    }
    // Wattd2_bf [512][6144] from W_attd[:, E:] (Korig = 2048)
    for (int i = idx; i < E*2048; i += stride) {
        int r = i >> 11, k = i & 2047;
        __nv_bfloat16 hi, lo;
        split_bf(W_attd[(size_t)r*(E+A) + E + k], hi, lo);
        __nv_bfloat16* d = g_wattd2_bf + (size_t)r * KBFA;
        d[k] = hi; d[k + 2048] = lo; d[k + 4096] = hi;
    }
}

__global__ void k_build_xs(const float* __restrict__ features,
                           const int*   __restrict__ captions,
                           const float* __restrict__ embed)
{
    pdl_wait();
    int idx = blockIdx.x * blockDim.x + threadIdx.x;
    int stride = gridDim.x * blockDim.x;
    for (int i = idx; i < TP1*B*E; i += stride) {
        int e  = i & (E - 1);
        int be = i >> 9;
        int b  = be & (B - 1);
        int t  = be >> 7;
        float v;
        if (t == 0) {
            v = features[b*E + e];
        } else {
            int tok = captions[b*T + (t - 1)];
            v = embed[(size_t)tok*E + e];
        }
        g_buf[XS_OFF + i] = v;
    }
}

// ---------------------------------------------------------------------------
// softmax(pan[t] + 4 comb slabs cols[0:A]) * cnn -> att (split-bf16 A-side)
// ---------------------------------------------------------------------------
__global__ void __launch_bounds__(256)
k_softmax_att(const float* __restrict__ pre,
              const float* __restrict__ slc,
              const float* __restrict__ cnn)
{
    pdl_wait();
    int b = blockIdx.x;
    int t = threadIdx.x;
    const size_t o0 = (size_t)b*A;
    const float* s0 = slc + (size_t)b*NC;
    const size_t SS = (size_t)B*NC;
    float v[8];
    float mx = -1e30f;
#pragma unroll
    for (int i = 0; i < 8; ++i) {
        int j = t + 256*i;
        float s = pre[o0 + j] + s0[j] + s0[j + SS] + s0[j + 2*SS] + s0[j + 3*SS];
        v[i] = s;
        mx = fmaxf(mx, s);
    }
    __shared__ float red[256];
    red[t] = mx; __syncthreads();
    for (int off = 128; off > 0; off >>= 1) {
        if (t < off) red[t] = fmaxf(red[t], red[t + off]);
        __syncthreads();
    }
    mx = red[0]; __syncthreads();

    float sum = 0.f;
#pragma unroll
    for (int i = 0; i < 8; ++i) {
        v[i] = expf(v[i] - mx);
        sum += v[i];
    }
    red[t] = sum; __syncthreads();
    for (int off = 128; off > 0; off >>= 1) {
        if (t < off) red[t] += red[t + off];
        __syncthreads();
    }
    float inv = 1.f / red[0];

    const float* cb = cnn + o0;
    __nv_bfloat16* ab = g_att_bf + (size_t)b * KBFA;
#pragma unroll
    for (int i = 0; i < 8; ++i) {
        int j = t + 256*i;
        float x = cb[j] * v[i] * inv;
        __nv_bfloat16 hi, lo;
        split_bf(x, hi, lo);
        ab[j] = hi; ab[j + 2048] = hi; ab[j + 4096] = lo;
    }
}

// x2 = pad[t] + sum of 32 slD slabs -> x2_bf (split A-side)
__global__ void __launch_bounds__(256)
k_reduce_attd(const float* __restrict__ pre,
              const float* __restrict__ slab)
{
    pdl_wait();
    int i = blockIdx.x * blockDim.x + threadIdx.x;
    if (i >= B*E) return;
    float s = pre[i];
#pragma unroll
    for (int z = 0; z < 32; ++z) s += slab[i + (size_t)z*B*E];
    int b = i >> 9, j = i & 511;
    __nv_bfloat16 hi, lo;
    split_bf(s, hi, lo);
    __nv_bfloat16* d = g_x2_bf + (size_t)b * KBF;
    d[j] = hi; d[j + 512] = hi; d[j + 1024] = lo;
}

// LSTM pointwise: gates = bsum + 4 comb slabs (cols A..) + 8 gate_x slabs.
// h written split-bf16 (next comb) and fp16 (logits row t).
__global__ void __launch_bounds__(256)
k_lstm_red(const float* __restrict__ slc,
           const float* __restrict__ slg,
           const float* __restrict__ bsum,
           float* __restrict__ c,
           __half* __restrict__ hid16)
{
    pdl_wait();
    int idx = blockIdx.x * blockDim.x + threadIdx.x;
    if (idx >= B*H) return;
    int b = idx >> 9;
    int j = idx & 511;
    float gi = bsum[j], gf = bsum[j + 512], gg = bsum[j + 1024], go = bsum[j + 1536];
#pragma unroll
    for (int z = 0; z < 4; ++z) {
        const float* gc = slc + (size_t)z*B*NC + (size_t)b*NC + A;
        gi += gc[j];  gf += gc[j + 512];
        gg += gc[j + 1024];  go += gc[j + 1536];
    }
#pragma unroll
    for (int z = 0; z < 8; ++z) {
        const float* gx = slg + (size_t)z*B*G4 + (size_t)b*G4;
        gi += gx[j];  gf += gx[j + 512];
        gg += gx[j + 1024];  go += gx[j + 1536];
    }
    float ig = 1.f / (1.f + expf(-gi));
    float fg = 1.f / (1.f + expf(-gf));
    float gt = tanhf(gg);
    float og = 1.f / (1.f + expf(-go));
    float cn = fg * c[idx] + ig * gt;
    float hn = og * tanhf(cn);
    c[idx] = cn;
    __nv_bfloat16 hi, lo;
    split_bf(hn, hi, lo);
    __nv_bfloat16* d = g_h_bf + (size_t)b * KBF;
    d[j] = hi; d[j + 512] = hi; d[j + 1024] = lo;
    hid16[(size_t)b * KH1 + j] = __float2half(hn);
}

// ---------------------------------------------------------------------------
// Host: PDL launch helper
// ---------------------------------------------------------------------------
template<typename F, typename... Args>
static inline void pdl_launch(F func, dim3 gd, dim3 bd, size_t sh, Args... args)
{
    cudaLaunchConfig_t cfg = {};
    cfg.gridDim = gd;
    cfg.blockDim = bd;
    cfg.dynamicSmemBytes = sh;
    cudaLaunchAttribute attr[1];
    attr[0].id = cudaLaunchAttributeProgrammaticStreamSerialization;
    attr[0].val.programmaticStreamSerializationAllowed = 1;
    cfg.attrs = attr;
    cfg.numAttrs = 1;
    cudaLaunchKernelEx(&cfg, func, args...);
}

// ---------------------------------------------------------------------------
// Host launch sequence (graph-capturable: kernel launches only)
// ---------------------------------------------------------------------------
extern "C" void kernel_launch(void* const* d_in, const int* in_sizes, int n_in,
                              void* d_out, int out_size)
{
    const float* features = (const float*)d_in[0];
    const float* cnn      = (const float*)d_in[1];
    const int*   captions = (const int*)  d_in[2];
    /* d_in[3] = lengths (unused: all T+1) */
    const float* embed    = (const float*)d_in[4];
    const float* W_ih     = (const float*)d_in[5];
    const float* W_hh     = (const float*)d_in[6];
    const float* b_ih     = (const float*)d_in[7];
    const float* b_hh     = (const float*)d_in[8];
    const float* W_attn   = (const float*)d_in[9];
    const float* b_attn   = (const float*)d_in[10];
    const float* W_attd   = (const float*)d_in[11];
    const float* b_attd   = (const float*)d_in[12];
    const float* W_out    = (const float*)d_in[13];
    const float* b_out    = (const float*)d_in[14];
    float* out = (float*)d_out;

    float* buf = nullptr;
    cudaGetSymbolAddress((void**)&buf, g_buf);
    __nv_bfloat16 *xs_bf, *wattn_bf, *wattd_bf, *h_bf, *x2_bf, *att_bf;
    __nv_bfloat16 *wcomb_bf, *wih_bf, *wattd2_bf;
    __half *hid_h, *wout_h;
    cudaGetSymbolAddress((void**)&xs_bf,     g_xs_bf);
    cudaGetSymbolAddress((void**)&wattn_bf,  g_wattn_bf);
    cudaGetSymbolAddress((void**)&wattd_bf,  g_wattd_bf);
    cudaGetSymbolAddress((void**)&h_bf,      g_h_bf);
    cudaGetSymbolAddress((void**)&att_bf,    g_att_bf);
    cudaGetSymbolAddress((void**)&x2_bf,     g_x2_bf);
    cudaGetSymbolAddress((void**)&wcomb_bf,  g_wcomb_bf);
    cudaGetSymbolAddress((void**)&wih_bf,    g_wih_bf);
    cudaGetSymbolAddress((void**)&wattd2_bf, g_wattd2_bf);
    cudaGetSymbolAddress((void**)&hid_h,     g_hid_h);
    cudaGetSymbolAddress((void**)&wout_h,    g_wout_h);

    cudaFuncSetAttribute(hmma_gemm<KBF, false>,
                         cudaFuncAttributeMaxDynamicSharedMemorySize, HSMEM);
    cudaFuncSetAttribute(hmma_gemm<KH1, true>,
                         cudaFuncAttributeMaxDynamicSharedMemorySize, HSMEM);
    cudaFuncSetAttribute(hmma_rec,
                         cudaFuncAttributeMaxDynamicSharedMemorySize, HSMEM);

    float* xs   = buf + XS_OFF;
    float* pan  = buf + PAN_OFF;
    float* pad  = buf + PAD_OFF;
    float* cbuf = buf + C_OFF;
    float* slC  = buf + SLC_OFF;
    float* slD  = buf + SLD_OFF;
    float* slG  = buf + SLG_OFF;
    float* bsum = buf + BS_OFF;

    // prep
    pdl_launch(k_prep, dim3(2048), dim3(256), 0,
               b_ih, b_hh, W_attn, W_hh, W_ih, W_attd);
    pdl_launch(k_build_xs, dim3(2048), dim3(256), 0, features, captions, embed);

    // conversions
    pdl_launch(k_split_a, dim3(4096), dim3(256), 0,
               (const float*)xs, xs_bf, (int)MALL);
    pdl_launch(k_split_b, dim3(2048), dim3(256), 0,
               W_attn, (int)(E + H), wattn_bf, (int)A, (int)A);
    pdl_launch(k_split_b, dim3(1024), dim3(256), 0,
               W_attd, (int)(E + A), wattd_bf, (int)E, (int)E);
    pdl_launch(k_split_b16, dim3(4096), dim3(256), 0,
               W_out, (int)H, wout_h, (int)V, (int)VPAD);

    // pan[t] = x_t @ W_attn[:, :E]^T + b_attn  (bf16 3-term)
    pdl_launch(hmma_gemm<KBF, false>, dim3(A / 128, MALL / 128), dim3(256),
               (size_t)HSMEM, pan, (int)A, (int)A,
               (const uint16_t*)xs_bf, (const uint16_t*)wattn_bf, b_attn);
    // pad[t] = x_t @ W_attd[:, :E]^T + b_attd  (bf16 3-term)
    pdl_launch(hmma_gemm<KBF, false>, dim3(E / 128, MALL / 128), dim3(256),
               (size_t)HSMEM, pad, (int)E, (int)E,
               (const uint16_t*)xs_bf, (const uint16_t*)wattd_bf, b_attd);

    const int NLSTM = (B*H + 255)/256;

    // t = 0: gate_x = xs0 @ W_ih^T (xs_bf rows 0..127); comb slabs zeroed
    pdl_launch(hmma_rec, dim3(G4/128, 1, 8), dim3(256), (size_t)HSMEM,
               slG, (int)G4, (const uint16_t*)xs_bf,
               (const uint16_t*)wih_bf, (int)KBF, (int)(KBF/8));
    pdl_launch(k_lstm_red, dim3(NLSTM), dim3(256), 0,
               (const float*)slC, (const float*)slG, (const float*)bsum,
               cbuf, hid_h);

    // t = 1..T
    for (int t = 1; t <= T; ++t) {
        // comb: [scores | gates_h] = h @ Wcomb^T  (splitK4 -> 128 blocks)
        pdl_launch(hmma_rec, dim3(NC/128, 1, 4), dim3(256), (size_t)HSMEM,
                   slC, (int)NC, (const uint16_t*)h_bf,
                   (const uint16_t*)wcomb_bf, (int)KBF, (int)(KBF/4));

        // softmax(pan[t] + slabs) * cnn -> att_bf
        pdl_launch(k_softmax_att, dim3(B), dim3(256), 0,
                   (const float*)(pan + (size_t)t*B*A), (const float*)slC, cnn);

        // attd: slD[z] = att @ W_attd[:, E:]^T  (splitK32 -> 128 blocks)
        pdl_launch(hmma_rec, dim3(E/128, 1, 32), dim3(256), (size_t)HSMEM,
                   slD, (int)E, (const uint16_t*)att_bf,
                   (const uint16_t*)wattd2_bf, (int)KBFA, (int)(KBFA/32));

        // x2 = pad[t] + sum slD -> x2_bf
        pdl_launch(k_reduce_attd, dim3((B*E + 255)/256), dim3(256), 0,
                   (const float*)(pad + (size_t)t*B*E), (const float*)slD);

        // gate_x: slG = x2 @ W_ih^T  (splitK8 -> 128 blocks)
        pdl_launch(hmma_rec, dim3(G4/128, 1, 8), dim3(256), (size_t)HSMEM,
                   slG, (int)G4, (const uint16_t*)x2_bf,
                   (const uint16_t*)wih_bf, (int)KBF, (int)(KBF/8));

        // LSTM pointwise; h -> split-bf16 + fp16 row t
        pdl_launch(k_lstm_red, dim3(NLSTM), dim3(256), 0,
                   (const float*)slC, (const float*)slG, (const float*)bsum,
                   cbuf, hid_h + (size_t)t*B*KH1);
    }

    // logits = hidden @ W_out^T + b_out  (fp16 1-term, K=512)
    pdl_launch(hmma_gemm<KH1, true>, dim3(VPAD / 128, MALL / 128), dim3(256),
               (size_t)HSMEM, out, (int)V, (int)V,
               (const uint16_t*)hid_h, (const uint16_t*)wout_h, b_out);
}